// round 1
// baseline (speedup 1.0000x reference)
#include <cuda_runtime.h>
#include <math.h>

#define IN_CH  128
#define ED_CH  64
#define HID_CH 256
#define K_CLS  1000
#define MAXN   50000
#define MAXB   128

// ---------------- scratch (static device globals; no allocation) ----------------
__device__ float    g_agg[MAXN * IN_CH];
__device__ float    g_h[MAXN * IN_CH];
__device__ float    g_t[MAXN * HID_CH];
__device__ float    g_h2[MAXN * HID_CH];
__device__ float    g_g1[MAXN * 128];
__device__ float    g_gate[MAXN];
__device__ unsigned g_gmax[MAXB];
__device__ float    g_denom[MAXB];
__device__ float    g_pnum[MAXB * HID_CH];
__device__ float    g_pooled[MAXB * HID_CH];
__device__ int      g_is64;

// ---------------- helpers ----------------
__device__ __forceinline__ unsigned fenc(float f) {
    unsigned u = __float_as_uint(f);
    return (u & 0x80000000u) ? ~u : (u | 0x80000000u);
}
__device__ __forceinline__ float fdec(unsigned u) {
    return __uint_as_float((u & 0x80000000u) ? (u ^ 0x80000000u) : ~u);
}
// vector reduction to global (PTX ISA 8.1+, sm_90+): 4 floats per instruction
__device__ __forceinline__ void red4(float* p, float a, float b, float c, float d) {
    asm volatile("red.global.add.v4.f32 [%0], {%1,%2,%3,%4};"
                 :: "l"(p), "f"(a), "f"(b), "f"(c), "f"(d) : "memory");
}
__device__ __forceinline__ long long load_index(const void* p, long i, int is64) {
    if (is64) return ((const long long*)p)[i];
    return (long long)((const int*)p)[i];
}

// ---------------- dtype sniff: int64 indices have all-zero odd 32-bit words ----------------
__global__ void sniff_kernel(const int* __restrict__ ei) {
    if (threadIdx.x == 0 && blockIdx.x == 0) {
        int nz = 0;
        for (int i = 0; i < 1024; i++) nz += (ei[2 * i + 1] != 0);
        g_is64 = (nz < 100) ? 1 : 0;
    }
}

// ---------------- init: zero accumulators ----------------
__global__ void init_kernel(int n) {
    int stride = gridDim.x * blockDim.x;
    int i = blockIdx.x * blockDim.x + threadIdx.x;
    int n4 = n * IN_CH / 4;
    float4 z = make_float4(0.f, 0.f, 0.f, 0.f);
    for (int j = i; j < n4; j += stride) ((float4*)g_agg)[j] = z;
    for (int j = i; j < MAXB * HID_CH; j += stride) g_pnum[j] = 0.f;
    if (i < MAXB) { g_denom[i] = 0.f; g_gmax[i] = 0u; }
}

// ---------------- edge phase: e = attr@We + be; m = relu(x[src]+e); scatter-add to agg[dst] ----------------
__global__ void __launch_bounds__(256) edge_kernel(
    const float* __restrict__ eattr, const void* __restrict__ ei,
    const float* __restrict__ x, const float* __restrict__ We,
    const float* __restrict__ be, int E)
{
    __shared__ float We_s[ED_CH * IN_CH];   // 32 KB
    __shared__ float be_s[IN_CH];
    __shared__ float attr_s[8][4][ED_CH];   // 8 KB
    for (int i = threadIdx.x; i < ED_CH * IN_CH; i += 256) We_s[i] = We[i];
    if (threadIdx.x < IN_CH) be_s[threadIdx.x] = be[threadIdx.x];
    __syncthreads();

    const int is64 = g_is64;
    const int lane = threadIdx.x & 31;
    const int warp = threadIdx.x >> 5;
    const int gw = blockIdx.x * 8 + warp;
    const int nw = gridDim.x * 8;
    const float4 bev = *(const float4*)&be_s[lane * 4];

    for (int base = gw * 4; base < E; base += nw * 4) {
        int ne = min(4, E - base);
        for (int e = 0; e < ne; e++) {
            const float* ar = eattr + (size_t)(base + e) * ED_CH;
            attr_s[warp][e][lane] = ar[lane];
            attr_s[warp][e][lane + 32] = ar[lane + 32];
        }
        __syncwarp();

        float4 acc[4];
        #pragma unroll
        for (int e = 0; e < 4; e++) acc[e] = bev;

        #pragma unroll 8
        for (int k = 0; k < ED_CH; k++) {
            float4 w = *(const float4*)&We_s[k * IN_CH + lane * 4];
            #pragma unroll
            for (int e = 0; e < 4; e++) {
                float a = attr_s[warp][e][k];
                acc[e].x += a * w.x; acc[e].y += a * w.y;
                acc[e].z += a * w.z; acc[e].w += a * w.w;
            }
        }

        #pragma unroll
        for (int e = 0; e < 4; e++) {
            if (e < ne) {
                long long s = load_index(ei, base + e, is64);
                long long d = load_index(ei, (long)E + base + e, is64);
                float4 xv = *(const float4*)&x[(size_t)s * IN_CH + lane * 4];
                float mx = fmaxf(xv.x + acc[e].x, 0.f);
                float my = fmaxf(xv.y + acc[e].y, 0.f);
                float mz = fmaxf(xv.z + acc[e].z, 0.f);
                float mw = fmaxf(xv.w + acc[e].w, 0.f);
                red4(&g_agg[(size_t)d * IN_CH + lane * 4], mx, my, mz, mw);
            }
        }
        __syncwarp();
    }
}

// ---------------- h = x + agg ----------------
__global__ void add_kernel(const float* __restrict__ x, int n4) {
    int i = blockIdx.x * blockDim.x + threadIdx.x;
    if (i < n4) {
        float4 a = ((const float4*)x)[i];
        float4 b = ((const float4*)g_agg)[i];
        ((float4*)g_h)[i] = make_float4(a.x + b.x, a.y + b.y, a.z + b.z, a.w + b.w);
    }
}

// ---------------- register-tiled fp32 GEMM: BM=BN=128, BK=16, TM=TN=8 ----------------
// MODE 0: t  = relu(h  @ W1  + b1)   K=128 N=256
// MODE 1: h2 =      t  @ W2  + b2    K=256 N=256
// MODE 2: g1 = relu(h2 @ Wg1 + bg1)  K=256 N=128
template <int MODE>
__global__ void __launch_bounds__(256) gemm_kernel(const float* __restrict__ W,
                                                   const float* __restrict__ bias, int M)
{
    constexpr int K = (MODE == 0) ? 128 : 256;
    constexpr int N = (MODE == 2) ? 128 : 256;
    constexpr bool RELU = (MODE != 1);
    const float* __restrict__ A = (MODE == 0) ? g_h : (MODE == 1) ? g_t : g_h2;
    float* __restrict__ C       = (MODE == 0) ? g_t : (MODE == 1) ? g_h2 : g_g1;

    __shared__ float As[16][128];
    __shared__ float Bs[16][128];
    int bm = blockIdx.y * 128;
    int bn = blockIdx.x * 128;
    int tid = threadIdx.x;
    int tx = tid & 15;
    int ty = tid >> 4;

    float acc[8][8];
    #pragma unroll
    for (int i = 0; i < 8; i++)
        #pragma unroll
        for (int j = 0; j < 8; j++) acc[i][j] = 0.f;

    for (int k0 = 0; k0 < K; k0 += 16) {
        #pragma unroll
        for (int i = 0; i < 2; i++) {   // A tile, stored k-major (transposed)
            int f = tid * 2 + i;
            int m = f >> 2;
            int kk = (f & 3) * 4;
            int gm = bm + m;
            float4 v = make_float4(0.f, 0.f, 0.f, 0.f);
            if (gm < M) v = *(const float4*)&A[(size_t)gm * K + k0 + kk];
            As[kk][m] = v.x; As[kk + 1][m] = v.y; As[kk + 2][m] = v.z; As[kk + 3][m] = v.w;
        }
        #pragma unroll
        for (int i = 0; i < 2; i++) {   // B tile, natural layout
            int f = tid * 2 + i;
            int kk = f >> 5;
            int nn = (f & 31) * 4;
            *(float4*)&Bs[kk][nn] = *(const float4*)&W[(size_t)(k0 + kk) * N + bn + nn];
        }
        __syncthreads();
        #pragma unroll
        for (int k = 0; k < 16; k++) {
            float a[8], b[8];
            *(float4*)&a[0] = *(float4*)&As[k][ty * 8];
            *(float4*)&a[4] = *(float4*)&As[k][ty * 8 + 4];
            *(float4*)&b[0] = *(float4*)&Bs[k][tx * 8];
            *(float4*)&b[4] = *(float4*)&Bs[k][tx * 8 + 4];
            #pragma unroll
            for (int i2 = 0; i2 < 8; i2++)
                #pragma unroll
                for (int j = 0; j < 8; j++) acc[i2][j] += a[i2] * b[j];
        }
        __syncthreads();
    }

    #pragma unroll
    for (int i2 = 0; i2 < 8; i2++) {
        int m = bm + ty * 8 + i2;
        if (m >= M) continue;
        #pragma unroll
        for (int j0 = 0; j0 < 8; j0 += 4) {
            int nn = bn + tx * 8 + j0;
            float4 v;
            v.x = acc[i2][j0 + 0] + bias[nn + 0];
            v.y = acc[i2][j0 + 1] + bias[nn + 1];
            v.z = acc[i2][j0 + 2] + bias[nn + 2];
            v.w = acc[i2][j0 + 3] + bias[nn + 3];
            if (RELU) {
                v.x = fmaxf(v.x, 0.f); v.y = fmaxf(v.y, 0.f);
                v.z = fmaxf(v.z, 0.f); v.w = fmaxf(v.w, 0.f);
            }
            *(float4*)&C[(size_t)m * N + nn] = v;
        }
    }
}

// ---------------- gate = g1 @ Wg2 + bg2  (warp per node) ----------------
__global__ void gate_kernel(const float* __restrict__ Wg2, const float* __restrict__ bg2, int n) {
    int w = (blockIdx.x * blockDim.x + threadIdx.x) >> 5;
    int lane = threadIdx.x & 31;
    if (w >= n) return;
    float4 a = *(const float4*)&g_g1[(size_t)w * 128 + lane * 4];
    float4 v = *(const float4*)&Wg2[lane * 4];
    float s = a.x * v.x + a.y * v.y + a.z * v.z + a.w * v.w;
    #pragma unroll
    for (int o = 16; o; o >>= 1) s += __shfl_xor_sync(0xffffffffu, s, o);
    if (lane == 0) g_gate[w] = s + bg2[0];
}

// ---------------- per-graph max of gate ----------------
__global__ void gmax_kernel(const void* __restrict__ batch, int n) {
    int i = blockIdx.x * blockDim.x + threadIdx.x;
    if (i >= n) return;
    int b = (int)load_index(batch, i, g_is64);
    atomicMax(&g_gmax[b], fenc(g_gate[i]));
}

// ---------------- softmax numerator + weighted sum (warp per node) ----------------
__global__ void gsum_kernel(const void* __restrict__ batch, int n) {
    int w = (blockIdx.x * blockDim.x + threadIdx.x) >> 5;
    int lane = threadIdx.x & 31;
    if (w >= n) return;
    int b = (int)load_index(batch, w, g_is64);
    float a = expf(g_gate[w] - fdec(g_gmax[b]));
    if (lane == 0) atomicAdd(&g_denom[b], a);
    const float* hr = &g_h2[(size_t)w * HID_CH + lane * 8];
    float4 h0 = *(const float4*)hr;
    float4 h1 = *(const float4*)(hr + 4);
    float* pr = &g_pnum[b * HID_CH + lane * 8];
    red4(pr, a * h0.x, a * h0.y, a * h0.z, a * h0.w);
    red4(pr + 4, a * h1.x, a * h1.y, a * h1.z, a * h1.w);
}

// ---------------- pooled = pnum / denom; write to output tail ----------------
__global__ void pool_kernel(float* __restrict__ out, int B) {
    int i = blockIdx.x * blockDim.x + threadIdx.x;
    if (i >= B * HID_CH) return;
    int b = i >> 8;
    float d = g_denom[b];
    float p = (d > 0.f) ? g_pnum[i] / d : 0.f;
    g_pooled[i] = p;
    out[(size_t)B * K_CLS + i] = p;
}

// ---------------- logits = pooled @ Wh + bh ----------------
__global__ void head_kernel(const float* __restrict__ Wh, const float* __restrict__ bh,
                            float* __restrict__ out) {
    __shared__ float p[HID_CH];
    int b = blockIdx.x;
    p[threadIdx.x] = g_pooled[b * HID_CH + threadIdx.x];
    __syncthreads();
    for (int k = threadIdx.x; k < K_CLS; k += 256) {
        float s = bh[k];
        #pragma unroll 8
        for (int c = 0; c < HID_CH; c++) s += p[c] * Wh[c * K_CLS + k];
        out[(size_t)b * K_CLS + k] = s;
    }
}

// ---------------- launch ----------------
extern "C" void kernel_launch(void* const* d_in, const int* in_sizes, int n_in,
                              void* d_out, int out_size) {
    const float* x     = (const float*)d_in[0];
    const void*  ei    = d_in[1];
    const float* eattr = (const float*)d_in[2];
    const void*  batch = d_in[3];
    const float* We    = (const float*)d_in[4];
    const float* be    = (const float*)d_in[5];
    const float* W1    = (const float*)d_in[6];
    const float* b1    = (const float*)d_in[7];
    const float* W2    = (const float*)d_in[8];
    const float* b2    = (const float*)d_in[9];
    const float* Wg1   = (const float*)d_in[10];
    const float* bg1   = (const float*)d_in[11];
    const float* Wg2   = (const float*)d_in[12];
    const float* bg2   = (const float*)d_in[13];
    const float* Wh    = (const float*)d_in[14];
    const float* bh    = (const float*)d_in[15];
    float* out = (float*)d_out;

    int n = in_sizes[0] / IN_CH;
    int E = in_sizes[2] / ED_CH;
    int B = out_size / (K_CLS + HID_CH);

    sniff_kernel<<<1, 32>>>((const int*)ei);
    init_kernel<<<2048, 256>>>(n);
    edge_kernel<<<592, 256>>>(eattr, ei, x, We, be, E);

    int n4 = n * IN_CH / 4;
    add_kernel<<<(n4 + 255) / 256, 256>>>(x, n4);

    int mb = (n + 127) / 128;
    gemm_kernel<0><<<dim3(2, mb), 256>>>(W1, b1, n);
    gemm_kernel<1><<<dim3(2, mb), 256>>>(W2, b2, n);
    gemm_kernel<2><<<dim3(1, mb), 256>>>(Wg1, bg1, n);

    int wblocks = (n * 32 + 255) / 256;
    gate_kernel<<<wblocks, 256>>>(Wg2, bg2, n);
    gmax_kernel<<<(n + 255) / 256, 256>>>(batch, n);
    gsum_kernel<<<wblocks, 256>>>(batch, n);
    pool_kernel<<<(B * HID_CH + 255) / 256, 256>>>(out, B);
    head_kernel<<<B, 256>>>(Wh, bh, out);
}

// round 2
// speedup vs baseline: 1.2373x; 1.2373x over previous
#include <cuda_runtime.h>
#include <math.h>

#define IN_CH  128
#define ED_CH  64
#define HID_CH 256
#define K_CLS  1000
#define MAXN   50000
#define MAXB   128

// ---------------- scratch (static device globals; no allocation) ----------------
__device__ float    g_agg[MAXN * IN_CH];
__device__ float    g_h[MAXN * IN_CH];
__device__ float    g_t[MAXN * HID_CH];
__device__ float    g_h2[MAXN * HID_CH];
__device__ float    g_g1[MAXN * 128];
__device__ float    g_gate[MAXN];
__device__ unsigned g_gmax[MAXB];
__device__ float    g_denom[MAXB];
__device__ float    g_pnum[MAXB * HID_CH];
__device__ float    g_pooled[MAXB * HID_CH];
__device__ int      g_is64;

// ---------------- helpers ----------------
__device__ __forceinline__ unsigned fenc(float f) {
    unsigned u = __float_as_uint(f);
    return (u & 0x80000000u) ? ~u : (u | 0x80000000u);
}
__device__ __forceinline__ float fdec(unsigned u) {
    return __uint_as_float((u & 0x80000000u) ? (u ^ 0x80000000u) : ~u);
}
__device__ __forceinline__ void red4(float* p, float a, float b, float c, float d) {
    asm volatile("red.global.add.v4.f32 [%0], {%1,%2,%3,%4};"
                 :: "l"(p), "f"(a), "f"(b), "f"(c), "f"(d) : "memory");
}
__device__ __forceinline__ long long load_index(const void* p, long i, int is64) {
    if (is64) return ((const long long*)p)[i];
    return (long long)((const int*)p)[i];
}
__device__ __forceinline__ unsigned f2tf(float f) {
    unsigned r;
    asm("cvt.rna.tf32.f32 %0, %1;" : "=r"(r) : "f"(f));
    return r;
}
__device__ __forceinline__ void mma8(float* c, const unsigned* a, const unsigned* b) {
    asm volatile("mma.sync.aligned.m16n8k8.row.col.f32.tf32.tf32.f32 "
                 "{%0,%1,%2,%3}, {%4,%5,%6,%7}, {%8,%9}, {%0,%1,%2,%3};"
                 : "+f"(c[0]), "+f"(c[1]), "+f"(c[2]), "+f"(c[3])
                 : "r"(a[0]), "r"(a[1]), "r"(a[2]), "r"(a[3]), "r"(b[0]), "r"(b[1]));
}

// ---------------- dtype sniff ----------------
__global__ void sniff_kernel(const int* __restrict__ ei) {
    if (threadIdx.x == 0 && blockIdx.x == 0) {
        int nz = 0;
        for (int i = 0; i < 1024; i++) nz += (ei[2 * i + 1] != 0);
        g_is64 = (nz < 100) ? 1 : 0;
    }
}

// ---------------- init: zero accumulators ----------------
__global__ void init_kernel(int n) {
    int stride = gridDim.x * blockDim.x;
    int i = blockIdx.x * blockDim.x + threadIdx.x;
    int n4 = n * IN_CH / 4;
    float4 z = make_float4(0.f, 0.f, 0.f, 0.f);
    for (int j = i; j < n4; j += stride) ((float4*)g_agg)[j] = z;
    for (int j = i; j < MAXB * HID_CH; j += stride) g_pnum[j] = 0.f;
    if (i < MAXB) { g_denom[i] = 0.f; g_gmax[i] = 0u; }
}

// ---------------- edge phase: tf32 tensor-core GEMM + fused gather/relu/scatter ----------------
// tile: 128 edges x 128 IN outputs, K=64
union EdgeSM {
    struct { unsigned As[128][36]; unsigned Bs[32][132]; } ab;  // 18KB + 16.9KB
    float Cs[64][132];                                          // 33.8KB
};

__global__ void __launch_bounds__(256, 1) edge_tf32(
    const float* __restrict__ eattr, const void* __restrict__ ei,
    const float* __restrict__ x, const float* __restrict__ We,
    const float* __restrict__ be, int E)
{
    __shared__ EdgeSM sm;
    __shared__ int s_src[128], s_dst[128];

    const int tid = threadIdx.x;
    const int lane = tid & 31, warp = tid >> 5;
    const int wm = warp & 3, wn = warp >> 2;
    const int r0 = lane >> 2, c0 = lane & 3;
    const int eb = blockIdx.x * 128;
    const int is64 = g_is64;

    if (tid < 128) {
        int eg = eb + tid;
        if (eg < E) {
            s_src[tid] = (int)load_index(ei, eg, is64);
            s_dst[tid] = (int)load_index(ei, (long)E + eg, is64);
        } else { s_src[tid] = 0; s_dst[tid] = 0; }
    }

    float acc[2][8][4];
    #pragma unroll
    for (int mi = 0; mi < 2; mi++)
        #pragma unroll
        for (int ni = 0; ni < 8; ni++)
            #pragma unroll
            for (int q = 0; q < 4; q++) acc[mi][ni][q] = 0.f;

    #pragma unroll
    for (int k0 = 0; k0 < ED_CH; k0 += 32) {
        // A tile: edge_attr rows (128 x 32)
        #pragma unroll
        for (int i = 0; i < 4; i++) {
            int f = tid + i * 256;
            int row = f >> 3, kk = (f & 7) * 4;
            int eg = eb + row;
            float4 v = make_float4(0.f, 0.f, 0.f, 0.f);
            if (eg < E) v = *(const float4*)&eattr[(size_t)eg * ED_CH + k0 + kk];
            sm.ab.As[row][kk] = f2tf(v.x); sm.ab.As[row][kk + 1] = f2tf(v.y);
            sm.ab.As[row][kk + 2] = f2tf(v.z); sm.ab.As[row][kk + 3] = f2tf(v.w);
        }
        // B tile: We (32 x 128)
        #pragma unroll
        for (int i = 0; i < 4; i++) {
            int f = tid + i * 256;
            int kk = f >> 5, n4 = (f & 31) * 4;
            float4 v = *(const float4*)&We[(size_t)(k0 + kk) * IN_CH + n4];
            sm.ab.Bs[kk][n4] = f2tf(v.x); sm.ab.Bs[kk][n4 + 1] = f2tf(v.y);
            sm.ab.Bs[kk][n4 + 2] = f2tf(v.z); sm.ab.Bs[kk][n4 + 3] = f2tf(v.w);
        }
        __syncthreads();
        #pragma unroll
        for (int ks = 0; ks < 4; ks++) {
            int k = ks * 8;
            unsigned a[2][4], b[8][2];
            #pragma unroll
            for (int mi = 0; mi < 2; mi++) {
                int rm = wm * 32 + mi * 16 + r0;
                a[mi][0] = sm.ab.As[rm][k + c0];
                a[mi][1] = sm.ab.As[rm + 8][k + c0];
                a[mi][2] = sm.ab.As[rm][k + c0 + 4];
                a[mi][3] = sm.ab.As[rm + 8][k + c0 + 4];
            }
            #pragma unroll
            for (int ni = 0; ni < 8; ni++) {
                int cn = wn * 64 + ni * 8 + r0;
                b[ni][0] = sm.ab.Bs[k + c0][cn];
                b[ni][1] = sm.ab.Bs[k + c0 + 4][cn];
            }
            #pragma unroll
            for (int mi = 0; mi < 2; mi++)
                #pragma unroll
                for (int ni = 0; ni < 8; ni++)
                    mma8(acc[mi][ni], a[mi], b[ni]);
        }
        __syncthreads();
    }

    const float4 bev = *(const float4*)&be[lane * 4];

    // epilogue in 2 phases of 64 edge-rows (Cs overlays As/Bs)
    #pragma unroll
    for (int p = 0; p < 2; p++) {
        if ((wm >> 1) == p) {
            #pragma unroll
            for (int mi = 0; mi < 2; mi++)
                #pragma unroll
                for (int ni = 0; ni < 8; ni++) {
                    int r = (wm & 1) * 32 + mi * 16 + r0;
                    int col = wn * 64 + ni * 8 + 2 * c0;
                    sm.Cs[r][col]     = acc[mi][ni][0];
                    sm.Cs[r][col + 1] = acc[mi][ni][1];
                    sm.Cs[r + 8][col]     = acc[mi][ni][2];
                    sm.Cs[r + 8][col + 1] = acc[mi][ni][3];
                }
        }
        __syncthreads();
        #pragma unroll 2
        for (int j = 0; j < 8; j++) {
            int el = warp * 8 + j;
            int eg = eb + p * 64 + el;
            if (eg < E) {
                int s = s_src[p * 64 + el];
                int d = s_dst[p * 64 + el];
                float4 cv = *(const float4*)&sm.Cs[el][lane * 4];
                float4 xv = *(const float4*)&x[(size_t)s * IN_CH + lane * 4];
                red4(&g_agg[(size_t)d * IN_CH + lane * 4],
                     fmaxf(cv.x + bev.x + xv.x, 0.f),
                     fmaxf(cv.y + bev.y + xv.y, 0.f),
                     fmaxf(cv.z + bev.z + xv.z, 0.f),
                     fmaxf(cv.w + bev.w + xv.w, 0.f));
            }
        }
        __syncthreads();
    }
}

// ---------------- h = x + agg ----------------
__global__ void add_kernel(const float* __restrict__ x, int n4) {
    int i = blockIdx.x * blockDim.x + threadIdx.x;
    if (i < n4) {
        float4 a = ((const float4*)x)[i];
        float4 b = ((const float4*)g_agg)[i];
        ((float4*)g_h)[i] = make_float4(a.x + b.x, a.y + b.y, a.z + b.z, a.w + b.w);
    }
}

// ---------------- tf32 tensor-core GEMM for node MLPs ----------------
// MODE 0: t  = relu(h  @ W1  + b1)   K=128 N=256
// MODE 1: h2 =      t  @ W2  + b2    K=256 N=256
// MODE 2: g1 = relu(h2 @ Wg1 + bg1)  K=256 N=128
template <int MODE>
__global__ void __launch_bounds__(256, 1) gemm_tf32(const float* __restrict__ W,
                                                    const float* __restrict__ bias, int M)
{
    constexpr int K = (MODE == 0) ? 128 : 256;
    constexpr int N = (MODE == 2) ? 128 : 256;
    constexpr bool RELU = (MODE != 1);
    const float* __restrict__ A = (MODE == 0) ? g_h : (MODE == 1) ? g_t : g_h2;
    float* __restrict__ C       = (MODE == 0) ? g_t : (MODE == 1) ? g_h2 : g_g1;

    __shared__ unsigned As[128][36];
    __shared__ unsigned Bs[32][132];

    const int tid = threadIdx.x;
    const int lane = tid & 31, warp = tid >> 5;
    const int wm = warp & 3, wn = warp >> 2;
    const int r0 = lane >> 2, c0 = lane & 3;
    const int bm = blockIdx.y * 128, bn = blockIdx.x * 128;

    float acc[2][8][4];
    #pragma unroll
    for (int mi = 0; mi < 2; mi++)
        #pragma unroll
        for (int ni = 0; ni < 8; ni++)
            #pragma unroll
            for (int q = 0; q < 4; q++) acc[mi][ni][q] = 0.f;

    for (int k0 = 0; k0 < K; k0 += 32) {
        #pragma unroll
        for (int i = 0; i < 4; i++) {
            int f = tid + i * 256;
            int row = f >> 3, kk = (f & 7) * 4;
            int gm = bm + row;
            float4 v = make_float4(0.f, 0.f, 0.f, 0.f);
            if (gm < M) v = *(const float4*)&A[(size_t)gm * K + k0 + kk];
            As[row][kk] = f2tf(v.x); As[row][kk + 1] = f2tf(v.y);
            As[row][kk + 2] = f2tf(v.z); As[row][kk + 3] = f2tf(v.w);
        }
        #pragma unroll
        for (int i = 0; i < 4; i++) {
            int f = tid + i * 256;
            int kk = f >> 5, n4 = (f & 31) * 4;
            float4 v = *(const float4*)&W[(size_t)(k0 + kk) * N + bn + n4];
            Bs[kk][n4] = f2tf(v.x); Bs[kk][n4 + 1] = f2tf(v.y);
            Bs[kk][n4 + 2] = f2tf(v.z); Bs[kk][n4 + 3] = f2tf(v.w);
        }
        __syncthreads();
        #pragma unroll
        for (int ks = 0; ks < 4; ks++) {
            int k = ks * 8;
            unsigned a[2][4], b[8][2];
            #pragma unroll
            for (int mi = 0; mi < 2; mi++) {
                int rm = wm * 32 + mi * 16 + r0;
                a[mi][0] = As[rm][k + c0];
                a[mi][1] = As[rm + 8][k + c0];
                a[mi][2] = As[rm][k + c0 + 4];
                a[mi][3] = As[rm + 8][k + c0 + 4];
            }
            #pragma unroll
            for (int ni = 0; ni < 8; ni++) {
                int cn = wn * 64 + ni * 8 + r0;
                b[ni][0] = Bs[k + c0][cn];
                b[ni][1] = Bs[k + c0 + 4][cn];
            }
            #pragma unroll
            for (int mi = 0; mi < 2; mi++)
                #pragma unroll
                for (int ni = 0; ni < 8; ni++)
                    mma8(acc[mi][ni], a[mi], b[ni]);
        }
        __syncthreads();
    }

    #pragma unroll
    for (int mi = 0; mi < 2; mi++) {
        #pragma unroll
        for (int ni = 0; ni < 8; ni++) {
            int row = bm + wm * 32 + mi * 16 + r0;
            int col = bn + wn * 64 + ni * 8 + 2 * c0;
            float bx = bias[col], by = bias[col + 1];
            float v0 = acc[mi][ni][0] + bx, v1 = acc[mi][ni][1] + by;
            float v2 = acc[mi][ni][2] + bx, v3 = acc[mi][ni][3] + by;
            if (RELU) {
                v0 = fmaxf(v0, 0.f); v1 = fmaxf(v1, 0.f);
                v2 = fmaxf(v2, 0.f); v3 = fmaxf(v3, 0.f);
            }
            if (row < M)     *(float2*)&C[(size_t)row * N + col]       = make_float2(v0, v1);
            if (row + 8 < M) *(float2*)&C[(size_t)(row + 8) * N + col] = make_float2(v2, v3);
        }
    }
}

// ---------------- gate = g1 @ Wg2 + bg2  (warp per node) ----------------
__global__ void gate_kernel(const float* __restrict__ Wg2, const float* __restrict__ bg2, int n) {
    int w = (blockIdx.x * blockDim.x + threadIdx.x) >> 5;
    int lane = threadIdx.x & 31;
    if (w >= n) return;
    float4 a = *(const float4*)&g_g1[(size_t)w * 128 + lane * 4];
    float4 v = *(const float4*)&Wg2[lane * 4];
    float s = a.x * v.x + a.y * v.y + a.z * v.z + a.w * v.w;
    #pragma unroll
    for (int o = 16; o; o >>= 1) s += __shfl_xor_sync(0xffffffffu, s, o);
    if (lane == 0) g_gate[w] = s + bg2[0];
}

// ---------------- per-graph max of gate ----------------
__global__ void gmax_kernel(const void* __restrict__ batch, int n) {
    int i = blockIdx.x * blockDim.x + threadIdx.x;
    if (i >= n) return;
    int b = (int)load_index(batch, i, g_is64);
    atomicMax(&g_gmax[b], fenc(g_gate[i]));
}

// ---------------- softmax numerator + weighted sum (warp per node) ----------------
__global__ void gsum_kernel(const void* __restrict__ batch, int n) {
    int w = (blockIdx.x * blockDim.x + threadIdx.x) >> 5;
    int lane = threadIdx.x & 31;
    if (w >= n) return;
    int b = (int)load_index(batch, w, g_is64);
    float a = expf(g_gate[w] - fdec(g_gmax[b]));
    if (lane == 0) atomicAdd(&g_denom[b], a);
    const float* hr = &g_h2[(size_t)w * HID_CH + lane * 8];
    float4 h0 = *(const float4*)hr;
    float4 h1 = *(const float4*)(hr + 4);
    float* pr = &g_pnum[b * HID_CH + lane * 8];
    red4(pr, a * h0.x, a * h0.y, a * h0.z, a * h0.w);
    red4(pr + 4, a * h1.x, a * h1.y, a * h1.z, a * h1.w);
}

// ---------------- pooled = pnum / denom; write to output tail ----------------
__global__ void pool_kernel(float* __restrict__ out, int B) {
    int i = blockIdx.x * blockDim.x + threadIdx.x;
    if (i >= B * HID_CH) return;
    int b = i >> 8;
    float d = g_denom[b];
    float p = (d > 0.f) ? g_pnum[i] / d : 0.f;
    g_pooled[i] = p;
    out[(size_t)B * K_CLS + i] = p;
}

// ---------------- logits = pooled @ Wh + bh ----------------
__global__ void head_kernel(const float* __restrict__ Wh, const float* __restrict__ bh,
                            float* __restrict__ out) {
    __shared__ float p[HID_CH];
    int b = blockIdx.x;
    p[threadIdx.x] = g_pooled[b * HID_CH + threadIdx.x];
    __syncthreads();
    for (int k = threadIdx.x; k < K_CLS; k += 256) {
        float s = bh[k];
        #pragma unroll 8
        for (int c = 0; c < HID_CH; c++) s += p[c] * Wh[c * K_CLS + k];
        out[(size_t)b * K_CLS + k] = s;
    }
}

// ---------------- launch ----------------
extern "C" void kernel_launch(void* const* d_in, const int* in_sizes, int n_in,
                              void* d_out, int out_size) {
    const float* x     = (const float*)d_in[0];
    const void*  ei    = d_in[1];
    const float* eattr = (const float*)d_in[2];
    const void*  batch = d_in[3];
    const float* We    = (const float*)d_in[4];
    const float* be    = (const float*)d_in[5];
    const float* W1    = (const float*)d_in[6];
    const float* b1    = (const float*)d_in[7];
    const float* W2    = (const float*)d_in[8];
    const float* b2    = (const float*)d_in[9];
    const float* Wg1   = (const float*)d_in[10];
    const float* bg1   = (const float*)d_in[11];
    const float* Wg2   = (const float*)d_in[12];
    const float* bg2   = (const float*)d_in[13];
    const float* Wh    = (const float*)d_in[14];
    const float* bh    = (const float*)d_in[15];
    float* out = (float*)d_out;

    int n = in_sizes[0] / IN_CH;
    int E = in_sizes[2] / ED_CH;
    int B = out_size / (K_CLS + HID_CH);

    sniff_kernel<<<1, 32>>>((const int*)ei);
    init_kernel<<<2048, 256>>>(n);
    edge_tf32<<<(E + 127) / 128, 256>>>(eattr, ei, x, We, be, E);

    int n4 = n * IN_CH / 4;
    add_kernel<<<(n4 + 255) / 256, 256>>>(x, n4);

    int mb = (n + 127) / 128;
    gemm_tf32<0><<<dim3(2, mb), 256>>>(W1, b1, n);
    gemm_tf32<1><<<dim3(2, mb), 256>>>(W2, b2, n);
    gemm_tf32<2><<<dim3(1, mb), 256>>>(Wg1, bg1, n);

    int wblocks = (n * 32 + 255) / 256;
    gate_kernel<<<wblocks, 256>>>(Wg2, bg2, n);
    gmax_kernel<<<(n + 255) / 256, 256>>>(batch, n);
    gsum_kernel<<<wblocks, 256>>>(batch, n);
    pool_kernel<<<(B * HID_CH + 255) / 256, 256>>>(out, B);
    head_kernel<<<B, 256>>>(Wh, bh, out);
}

// round 3
// speedup vs baseline: 1.7052x; 1.3782x over previous
#include <cuda_runtime.h>
#include <math.h>

#define IN_CH  128
#define ED_CH  64
#define HID_CH 256
#define K_CLS  1000
#define MAXN   50000
#define MAXB   128

// ---------------- scratch (static device globals; no allocation) ----------------
__device__ float    g_agg[MAXN * IN_CH];     // init = x, edge adds messages -> becomes h
__device__ float    g_t[MAXN * HID_CH];
__device__ float    g_h2[MAXN * HID_CH];
__device__ float    g_gate[MAXN];
__device__ unsigned g_gmax[MAXB];
__device__ float    g_denom[MAXB];
__device__ float    g_pnum[MAXB * HID_CH];
__device__ float    g_pooled[MAXB * HID_CH];
__device__ int      g_is64;

// ---------------- helpers ----------------
__device__ __forceinline__ unsigned fenc(float f) {
    unsigned u = __float_as_uint(f);
    return (u & 0x80000000u) ? ~u : (u | 0x80000000u);
}
__device__ __forceinline__ float fdec(unsigned u) {
    return __uint_as_float((u & 0x80000000u) ? (u ^ 0x80000000u) : ~u);
}
__device__ __forceinline__ void red4(float* p, float a, float b, float c, float d) {
    asm volatile("red.global.add.v4.f32 [%0], {%1,%2,%3,%4};"
                 :: "l"(p), "f"(a), "f"(b), "f"(c), "f"(d) : "memory");
}
__device__ __forceinline__ long long load_index(const void* p, long i, int is64) {
    if (is64) return ((const long long*)p)[i];
    return (long long)((const int*)p)[i];
}
__device__ __forceinline__ unsigned f2tf(float f) {
    unsigned r;
    asm("cvt.rna.tf32.f32 %0, %1;" : "=r"(r) : "f"(f));
    return r;
}
__device__ __forceinline__ void mma8(float* c, const unsigned* a, const unsigned* b) {
    asm volatile("mma.sync.aligned.m16n8k8.row.col.f32.tf32.tf32.f32 "
                 "{%0,%1,%2,%3}, {%4,%5,%6,%7}, {%8,%9}, {%0,%1,%2,%3};"
                 : "+f"(c[0]), "+f"(c[1]), "+f"(c[2]), "+f"(c[3])
                 : "r"(a[0]), "r"(a[1]), "r"(a[2]), "r"(a[3]), "r"(b[0]), "r"(b[1]));
}

// shared smem union for GEMM-style kernels: mainloop tiles overlay the epilogue C tile
union GemmSM {
    struct { unsigned As[128][36]; unsigned Bs[32][132]; } ab;  // 18KB + 16.9KB
    float Cs[64][132];                                          // 33.8KB
};

// ---------------- init: g_agg = x, zero pool accumulators, sniff index dtype ----------------
__global__ void init_kernel(const float* __restrict__ x, const int* __restrict__ ei, int n) {
    int stride = gridDim.x * blockDim.x;
    int i = blockIdx.x * blockDim.x + threadIdx.x;
    int n4 = n * IN_CH / 4;
    for (int j = i; j < n4; j += stride) ((float4*)g_agg)[j] = ((const float4*)x)[j];
    if (i < MAXB * HID_CH) g_pnum[i] = 0.f;
    if (i < MAXB) { g_denom[i] = 0.f; g_gmax[i] = 0u; }
    if (i == 0) {
        int nz = 0;
        #pragma unroll 8
        for (int k = 0; k < 256; k++) nz += (ei[2 * k + 1] != 0);
        g_is64 = (nz < 16) ? 1 : 0;
    }
}

// ---------------- edge phase: tf32 tensor-core GEMM + fused gather/relu/scatter ----------------
// tile: 128 edges x 128 IN outputs, K=64;  scatter adds into g_agg (pre-seeded with x)
__global__ void __launch_bounds__(256) edge_tf32(
    const float* __restrict__ eattr, const void* __restrict__ ei,
    const float* __restrict__ x, const float* __restrict__ We,
    const float* __restrict__ be, int E)
{
    __shared__ GemmSM sm;
    __shared__ int s_src[128], s_dst[128];

    const int tid = threadIdx.x;
    const int lane = tid & 31, warp = tid >> 5;
    const int wm = warp & 3, wn = warp >> 2;
    const int r0 = lane >> 2, c0 = lane & 3;
    const int eb = blockIdx.x * 128;
    const int is64 = g_is64;

    if (tid < 128) {
        int eg = eb + tid;
        if (eg < E) {
            s_src[tid] = (int)load_index(ei, eg, is64);
            s_dst[tid] = (int)load_index(ei, (long)E + eg, is64);
        } else { s_src[tid] = 0; s_dst[tid] = 0; }
    }

    float acc[2][8][4];
    #pragma unroll
    for (int mi = 0; mi < 2; mi++)
        #pragma unroll
        for (int ni = 0; ni < 8; ni++)
            #pragma unroll
            for (int q = 0; q < 4; q++) acc[mi][ni][q] = 0.f;

    #pragma unroll
    for (int k0 = 0; k0 < ED_CH; k0 += 32) {
        #pragma unroll
        for (int i = 0; i < 4; i++) {   // A: edge_attr (128 x 32)
            int f = tid + i * 256;
            int row = f >> 3, kk = (f & 7) * 4;
            int eg = eb + row;
            float4 v = make_float4(0.f, 0.f, 0.f, 0.f);
            if (eg < E) v = *(const float4*)&eattr[(size_t)eg * ED_CH + k0 + kk];
            sm.ab.As[row][kk] = f2tf(v.x); sm.ab.As[row][kk + 1] = f2tf(v.y);
            sm.ab.As[row][kk + 2] = f2tf(v.z); sm.ab.As[row][kk + 3] = f2tf(v.w);
        }
        #pragma unroll
        for (int i = 0; i < 4; i++) {   // B: We (32 x 128)
            int f = tid + i * 256;
            int kk = f >> 5, n4 = (f & 31) * 4;
            float4 v = *(const float4*)&We[(size_t)(k0 + kk) * IN_CH + n4];
            sm.ab.Bs[kk][n4] = f2tf(v.x); sm.ab.Bs[kk][n4 + 1] = f2tf(v.y);
            sm.ab.Bs[kk][n4 + 2] = f2tf(v.z); sm.ab.Bs[kk][n4 + 3] = f2tf(v.w);
        }
        __syncthreads();
        #pragma unroll
        for (int ks = 0; ks < 4; ks++) {
            int k = ks * 8;
            unsigned a[2][4], b[8][2];
            #pragma unroll
            for (int mi = 0; mi < 2; mi++) {
                int rm = wm * 32 + mi * 16 + r0;
                a[mi][0] = sm.ab.As[rm][k + c0];
                a[mi][1] = sm.ab.As[rm + 8][k + c0];
                a[mi][2] = sm.ab.As[rm][k + c0 + 4];
                a[mi][3] = sm.ab.As[rm + 8][k + c0 + 4];
            }
            #pragma unroll
            for (int ni = 0; ni < 8; ni++) {
                int cn = wn * 64 + ni * 8 + r0;
                b[ni][0] = sm.ab.Bs[k + c0][cn];
                b[ni][1] = sm.ab.Bs[k + c0 + 4][cn];
            }
            #pragma unroll
            for (int mi = 0; mi < 2; mi++)
                #pragma unroll
                for (int ni = 0; ni < 8; ni++)
                    mma8(acc[mi][ni], a[mi], b[ni]);
        }
        __syncthreads();
    }

    const float4 bev = *(const float4*)&be[lane * 4];

    // epilogue in 2 phases of 64 edge-rows (Cs overlays As/Bs)
    #pragma unroll
    for (int p = 0; p < 2; p++) {
        if ((wm >> 1) == p) {
            #pragma unroll
            for (int mi = 0; mi < 2; mi++)
                #pragma unroll
                for (int ni = 0; ni < 8; ni++) {
                    int r = (wm & 1) * 32 + mi * 16 + r0;
                    int col = wn * 64 + ni * 8 + 2 * c0;
                    sm.Cs[r][col]         = acc[mi][ni][0];
                    sm.Cs[r][col + 1]     = acc[mi][ni][1];
                    sm.Cs[r + 8][col]     = acc[mi][ni][2];
                    sm.Cs[r + 8][col + 1] = acc[mi][ni][3];
                }
        }
        __syncthreads();
        // batched gather (MLP=4) then scatter
        #pragma unroll
        for (int half = 0; half < 2; half++) {
            float4 cv[4], xv[4];
            int dd[4], ok[4];
            #pragma unroll
            for (int j = 0; j < 4; j++) {
                int el = warp * 8 + half * 4 + j;
                int eg = eb + p * 64 + el;
                ok[j] = (eg < E);
                int s = s_src[p * 64 + el];
                dd[j] = s_dst[p * 64 + el];
                cv[j] = *(const float4*)&sm.Cs[el][lane * 4];
                xv[j] = ok[j] ? *(const float4*)&x[(size_t)s * IN_CH + lane * 4]
                              : make_float4(0.f, 0.f, 0.f, 0.f);
            }
            #pragma unroll
            for (int j = 0; j < 4; j++) {
                if (ok[j]) {
                    red4(&g_agg[(size_t)dd[j] * IN_CH + lane * 4],
                         fmaxf(cv[j].x + bev.x + xv[j].x, 0.f),
                         fmaxf(cv[j].y + bev.y + xv[j].y, 0.f),
                         fmaxf(cv[j].z + bev.z + xv[j].z, 0.f),
                         fmaxf(cv[j].w + bev.w + xv[j].w, 0.f));
                }
            }
        }
        __syncthreads();
    }
}

// ---------------- tf32 tensor-core GEMM for node MLPs ----------------
// MODE 0: t  = relu(h  @ W1  + b1)   K=128 N=256   (h == g_agg)
// MODE 1: h2 =      t  @ W2  + b2    K=256 N=256
// MODE 2: gate = relu(h2 @ Wg1 + bg1) @ Wg2 + bg2  K=256 N=128 (fused, writes g_gate only)
template <int MODE>
__global__ void __launch_bounds__(256) gemm_tf32(const float* __restrict__ W,
                                                 const float* __restrict__ bias,
                                                 const float* __restrict__ Wg2,
                                                 const float* __restrict__ bg2, int M)
{
    constexpr int K = (MODE == 0) ? 128 : 256;
    constexpr int N = (MODE == 2) ? 128 : 256;
    const float* __restrict__ A = (MODE == 0) ? g_agg : (MODE == 1) ? g_t : g_h2;
    float* __restrict__ C       = (MODE == 0) ? g_t : g_h2;   // unused for MODE 2

    __shared__ GemmSM sm;

    const int tid = threadIdx.x;
    const int lane = tid & 31, warp = tid >> 5;
    const int wm = warp & 3, wn = warp >> 2;
    const int r0 = lane >> 2, c0 = lane & 3;
    const int bm = blockIdx.y * 128, bn = blockIdx.x * 128;

    float acc[2][8][4];
    #pragma unroll
    for (int mi = 0; mi < 2; mi++)
        #pragma unroll
        for (int ni = 0; ni < 8; ni++)
            #pragma unroll
            for (int q = 0; q < 4; q++) acc[mi][ni][q] = 0.f;

    for (int k0 = 0; k0 < K; k0 += 32) {
        #pragma unroll
        for (int i = 0; i < 4; i++) {
            int f = tid + i * 256;
            int row = f >> 3, kk = (f & 7) * 4;
            int gm = bm + row;
            float4 v = make_float4(0.f, 0.f, 0.f, 0.f);
            if (gm < M) v = *(const float4*)&A[(size_t)gm * K + k0 + kk];
            sm.ab.As[row][kk] = f2tf(v.x); sm.ab.As[row][kk + 1] = f2tf(v.y);
            sm.ab.As[row][kk + 2] = f2tf(v.z); sm.ab.As[row][kk + 3] = f2tf(v.w);
        }
        #pragma unroll
        for (int i = 0; i < 4; i++) {
            int f = tid + i * 256;
            int kk = f >> 5, n4 = (f & 31) * 4;
            float4 v = *(const float4*)&W[(size_t)(k0 + kk) * N + bn + n4];
            sm.ab.Bs[kk][n4] = f2tf(v.x); sm.ab.Bs[kk][n4 + 1] = f2tf(v.y);
            sm.ab.Bs[kk][n4 + 2] = f2tf(v.z); sm.ab.Bs[kk][n4 + 3] = f2tf(v.w);
        }
        __syncthreads();
        #pragma unroll
        for (int ks = 0; ks < 4; ks++) {
            int k = ks * 8;
            unsigned a[2][4], b[8][2];
            #pragma unroll
            for (int mi = 0; mi < 2; mi++) {
                int rm = wm * 32 + mi * 16 + r0;
                a[mi][0] = sm.ab.As[rm][k + c0];
                a[mi][1] = sm.ab.As[rm + 8][k + c0];
                a[mi][2] = sm.ab.As[rm][k + c0 + 4];
                a[mi][3] = sm.ab.As[rm + 8][k + c0 + 4];
            }
            #pragma unroll
            for (int ni = 0; ni < 8; ni++) {
                int cn = wn * 64 + ni * 8 + r0;
                b[ni][0] = sm.ab.Bs[k + c0][cn];
                b[ni][1] = sm.ab.Bs[k + c0 + 4][cn];
            }
            #pragma unroll
            for (int mi = 0; mi < 2; mi++)
                #pragma unroll
                for (int ni = 0; ni < 8; ni++)
                    mma8(acc[mi][ni], a[mi], b[ni]);
        }
        __syncthreads();
    }

    if constexpr (MODE != 2) {
        constexpr bool RELU = (MODE == 0);
        #pragma unroll
        for (int mi = 0; mi < 2; mi++) {
            #pragma unroll
            for (int ni = 0; ni < 8; ni++) {
                int row = bm + wm * 32 + mi * 16 + r0;
                int col = bn + wn * 64 + ni * 8 + 2 * c0;
                float bx = bias[col], by = bias[col + 1];
                float v0 = acc[mi][ni][0] + bx, v1 = acc[mi][ni][1] + by;
                float v2 = acc[mi][ni][2] + bx, v3 = acc[mi][ni][3] + by;
                if (RELU) {
                    v0 = fmaxf(v0, 0.f); v1 = fmaxf(v1, 0.f);
                    v2 = fmaxf(v2, 0.f); v3 = fmaxf(v3, 0.f);
                }
                if (row < M)     *(float2*)&C[(size_t)row * N + col]       = make_float2(v0, v1);
                if (row + 8 < M) *(float2*)&C[(size_t)(row + 8) * N + col] = make_float2(v2, v3);
            }
        }
    } else {
        // fused gate: g1 tile (128 x 128) -> smem in 2 phases, warp-per-row dot with Wg2
        const float4 wgv = *(const float4*)&Wg2[lane * 4];
        const float bg2v = bg2[0];
        #pragma unroll
        for (int p = 0; p < 2; p++) {
            if ((wm >> 1) == p) {
                #pragma unroll
                for (int mi = 0; mi < 2; mi++)
                    #pragma unroll
                    for (int ni = 0; ni < 8; ni++) {
                        int r = (wm & 1) * 32 + mi * 16 + r0;
                        int col = wn * 64 + ni * 8 + 2 * c0;
                        float bx = bias[col], by = bias[col + 1];
                        sm.Cs[r][col]         = fmaxf(acc[mi][ni][0] + bx, 0.f);
                        sm.Cs[r][col + 1]     = fmaxf(acc[mi][ni][1] + by, 0.f);
                        sm.Cs[r + 8][col]     = fmaxf(acc[mi][ni][2] + bx, 0.f);
                        sm.Cs[r + 8][col + 1] = fmaxf(acc[mi][ni][3] + by, 0.f);
                    }
            }
            __syncthreads();
            #pragma unroll 2
            for (int j = 0; j < 8; j++) {
                int el = warp * 8 + j;
                int row = bm + p * 64 + el;
                if (row < M) {
                    float4 cvv = *(const float4*)&sm.Cs[el][lane * 4];
                    float s = cvv.x * wgv.x + cvv.y * wgv.y + cvv.z * wgv.z + cvv.w * wgv.w;
                    #pragma unroll
                    for (int o = 16; o; o >>= 1) s += __shfl_xor_sync(0xffffffffu, s, o);
                    if (lane == 0) g_gate[row] = s + bg2v;
                }
            }
            __syncthreads();
        }
    }
}

// ---------------- per-graph max of gate ----------------
__global__ void gmax_kernel(const void* __restrict__ batch, int n) {
    int i = blockIdx.x * blockDim.x + threadIdx.x;
    if (i >= n) return;
    int b = (int)load_index(batch, i, g_is64);
    atomicMax(&g_gmax[b], fenc(g_gate[i]));
}

// ---------------- softmax numerator + weighted sum: warp strips with run-length flush ----------------
__global__ void gsum_kernel(const void* __restrict__ batch, int n) {
    int w = (blockIdx.x * blockDim.x + threadIdx.x) >> 5;
    int lane = threadIdx.x & 31;
    int W = (gridDim.x * blockDim.x) >> 5;
    int L = (n + W - 1) / W;
    int s0 = w * L, e0 = min(s0 + L, n);
    if (s0 >= e0) return;
    const int is64 = g_is64;

    int bcur = (int)load_index(batch, s0, is64);
    float r[8];
    #pragma unroll
    for (int q = 0; q < 8; q++) r[q] = 0.f;
    float dsum = 0.f;

    for (int i = s0; i < e0; i++) {
        int b = (int)load_index(batch, i, is64);
        if (b != bcur) {
            float* pr = &g_pnum[bcur * HID_CH + lane * 8];
            red4(pr, r[0], r[1], r[2], r[3]);
            red4(pr + 4, r[4], r[5], r[6], r[7]);
            if (lane == 0) atomicAdd(&g_denom[bcur], dsum);
            #pragma unroll
            for (int q = 0; q < 8; q++) r[q] = 0.f;
            dsum = 0.f;
            bcur = b;
        }
        float a = expf(g_gate[i] - fdec(g_gmax[b]));
        const float* hr = &g_h2[(size_t)i * HID_CH + lane * 8];
        float4 h0 = *(const float4*)hr;
        float4 h1 = *(const float4*)(hr + 4);
        r[0] += a * h0.x; r[1] += a * h0.y; r[2] += a * h0.z; r[3] += a * h0.w;
        r[4] += a * h1.x; r[5] += a * h1.y; r[6] += a * h1.z; r[7] += a * h1.w;
        dsum += a;
    }
    float* pr = &g_pnum[bcur * HID_CH + lane * 8];
    red4(pr, r[0], r[1], r[2], r[3]);
    red4(pr + 4, r[4], r[5], r[6], r[7]);
    if (lane == 0) atomicAdd(&g_denom[bcur], dsum);
}

// ---------------- pooled = pnum / denom; write to output tail ----------------
__global__ void pool_kernel(float* __restrict__ out, int B) {
    int i = blockIdx.x * blockDim.x + threadIdx.x;
    if (i >= B * HID_CH) return;
    int b = i >> 8;
    float d = g_denom[b];
    float p = (d > 0.f) ? g_pnum[i] / d : 0.f;
    g_pooled[i] = p;
    out[(size_t)B * K_CLS + i] = p;
}

// ---------------- logits = pooled @ Wh + bh  (8 graphs per block, Wh reused 8x) ----------------
__global__ void __launch_bounds__(128) head_kernel(const float* __restrict__ Wh,
                                                   const float* __restrict__ bh,
                                                   float* __restrict__ out, int B) {
    __shared__ float p[8][HID_CH];   // 8 KB
    int kb = blockIdx.x * 128 + threadIdx.x;
    int b0 = blockIdx.y * 8;
    int nb = min(8, B - b0);
    for (int i = threadIdx.x; i < nb * HID_CH; i += 128)
        p[i >> 8][i & 255] = g_pooled[(b0 + (i >> 8)) * HID_CH + (i & 255)];
    __syncthreads();
    if (kb >= K_CLS) return;
    float acc[8];
    #pragma unroll
    for (int j = 0; j < 8; j++) acc[j] = 0.f;
    #pragma unroll 4
    for (int c = 0; c < HID_CH; c++) {
        float wv = Wh[(size_t)c * K_CLS + kb];
        #pragma unroll
        for (int j = 0; j < 8; j++) acc[j] += p[j][c] * wv;
    }
    float bv = bh[kb];
    for (int j = 0; j < nb; j++)
        out[(size_t)(b0 + j) * K_CLS + kb] = acc[j] + bv;
}

// ---------------- launch ----------------
extern "C" void kernel_launch(void* const* d_in, const int* in_sizes, int n_in,
                              void* d_out, int out_size) {
    const float* x     = (const float*)d_in[0];
    const void*  ei    = d_in[1];
    const float* eattr = (const float*)d_in[2];
    const void*  batch = d_in[3];
    const float* We    = (const float*)d_in[4];
    const float* be    = (const float*)d_in[5];
    const float* W1    = (const float*)d_in[6];
    const float* b1    = (const float*)d_in[7];
    const float* W2    = (const float*)d_in[8];
    const float* b2    = (const float*)d_in[9];
    const float* Wg1   = (const float*)d_in[10];
    const float* bg1   = (const float*)d_in[11];
    const float* Wg2   = (const float*)d_in[12];
    const float* bg2   = (const float*)d_in[13];
    const float* Wh    = (const float*)d_in[14];
    const float* bh    = (const float*)d_in[15];
    float* out = (float*)d_out;

    int n = in_sizes[0] / IN_CH;
    int E = in_sizes[2] / ED_CH;
    int B = out_size / (K_CLS + HID_CH);

    init_kernel<<<2048, 256>>>(x, (const int*)ei, n);
    edge_tf32<<<(E + 127) / 128, 256>>>(eattr, ei, x, We, be, E);

    int mb = (n + 127) / 128;
    gemm_tf32<0><<<dim3(2, mb), 256>>>(W1, b1, nullptr, nullptr, n);
    gemm_tf32<1><<<dim3(2, mb), 256>>>(W2, b2, nullptr, nullptr, n);
    gemm_tf32<2><<<dim3(1, mb), 256>>>(Wg1, bg1, Wg2, bg2, n);

    gmax_kernel<<<(n + 255) / 256, 256>>>(batch, n);
    gsum_kernel<<<400, 256>>>(batch, n);
    pool_kernel<<<(B * HID_CH + 255) / 256, 256>>>(out, B);
    head_kernel<<<dim3(8, (B + 7) / 8), 128>>>(Wh, bh, out, B);
}

// round 4
// speedup vs baseline: 2.2734x; 1.3332x over previous
#include <cuda_runtime.h>
#include <math.h>

#define IN_CH  128
#define ED_CH  64
#define HID_CH 256
#define K_CLS  1000
#define MAXN   50000
#define MAXB   128

// transposed tf32 weights: [n][k] layouts
#define WE_T_OFF  0          // 128 x 64
#define W1_T_OFF  8192       // 256 x 128
#define W2_T_OFF  40960      // 256 x 256
#define WG1_T_OFF 106496     // 128 x 256

// ---------------- scratch (static device globals; no allocation) ----------------
__device__ float    g_agg[MAXN * IN_CH];     // init = x, edge adds messages -> becomes h
__device__ float    g_t[MAXN * HID_CH];
__device__ float    g_h2[MAXN * HID_CH];
__device__ float    g_gate[MAXN];
__device__ unsigned g_gmax[MAXB];
__device__ float    g_denom[MAXB];
__device__ float    g_pnum[MAXB * HID_CH];
__device__ float    g_pooled[MAXB * HID_CH];
__device__ unsigned g_wt[139264];
__device__ int      g_is64;

// ---------------- helpers ----------------
__device__ __forceinline__ unsigned fenc(float f) {
    unsigned u = __float_as_uint(f);
    return (u & 0x80000000u) ? ~u : (u | 0x80000000u);
}
__device__ __forceinline__ float fdec(unsigned u) {
    return __uint_as_float((u & 0x80000000u) ? (u ^ 0x80000000u) : ~u);
}
__device__ __forceinline__ void red4(float* p, float a, float b, float c, float d) {
    asm volatile("red.global.add.v4.f32 [%0], {%1,%2,%3,%4};"
                 :: "l"(p), "f"(a), "f"(b), "f"(c), "f"(d) : "memory");
}
__device__ __forceinline__ long long load_index(const void* p, long i, int is64) {
    if (is64) return ((const long long*)p)[i];
    return (long long)((const int*)p)[i];
}
__device__ __forceinline__ unsigned f2tf(float f) {
    unsigned r;
    asm("cvt.rna.tf32.f32 %0, %1;" : "=r"(r) : "f"(f));
    return r;
}
__device__ __forceinline__ void mma8(float* c, const unsigned* a, const unsigned* b) {
    asm volatile("mma.sync.aligned.m16n8k8.row.col.f32.tf32.tf32.f32 "
                 "{%0,%1,%2,%3}, {%4,%5,%6,%7}, {%8,%9}, {%0,%1,%2,%3};"
                 : "+f"(c[0]), "+f"(c[1]), "+f"(c[2]), "+f"(c[3])
                 : "r"(a[0]), "r"(a[1]), "r"(a[2]), "r"(a[3]), "r"(b[0]), "r"(b[1]));
}
__device__ __forceinline__ void ldsm4(unsigned* r, unsigned addr) {
    asm volatile("ldmatrix.sync.aligned.m8n8.x4.shared.b16 {%0,%1,%2,%3}, [%4];"
                 : "=r"(r[0]), "=r"(r[1]), "=r"(r[2]), "=r"(r[3]) : "r"(addr));
}
__device__ __forceinline__ void cpasync16(unsigned saddr, const void* g) {
    asm volatile("cp.async.cg.shared.global [%0], [%1], 16;" :: "r"(saddr), "l"(g) : "memory");
}
__device__ __forceinline__ void cp_commit_wait() {
    asm volatile("cp.async.commit_group;\ncp.async.wait_group 0;" ::: "memory");
}

// smem union: mainloop tiles overlay the epilogue C tile
union GemmSM {
    struct { unsigned As[128 * 36]; unsigned Bst[128 * 36]; } ab;  // 36.9 KB
    float Cs[64 * 132];                                            // 33.8 KB
};

// ---------------- weight prep: Wt[n][k] = tf32(W[k][n]) ----------------
__global__ void prep_kernel(const float* __restrict__ W, int K, int N, int dstoff) {
    __shared__ float t[32][33];
    unsigned* dst = g_wt + dstoff;
    int n0 = blockIdx.x * 32, k0 = blockIdx.y * 32;
    for (int i = threadIdx.y; i < 32; i += 8)
        t[i][threadIdx.x] = W[(size_t)(k0 + i) * N + n0 + threadIdx.x];
    __syncthreads();
    for (int i = threadIdx.y; i < 32; i += 8)
        dst[(size_t)(n0 + i) * K + k0 + threadIdx.x] = f2tf(t[threadIdx.x][i]);
}

// ---------------- init: g_agg = x, zero pool accumulators, sniff index dtype ----------------
__global__ void init_kernel(const float* __restrict__ x, const int* __restrict__ ei, int n) {
    int stride = gridDim.x * blockDim.x;
    int i = blockIdx.x * blockDim.x + threadIdx.x;
    int n4 = n * IN_CH / 4;
    for (int j = i; j < n4; j += stride) ((float4*)g_agg)[j] = ((const float4*)x)[j];
    if (i < MAXB * HID_CH) g_pnum[i] = 0.f;
    if (i < MAXB) { g_denom[i] = 0.f; g_gmax[i] = 0u; }
    if (i == 0) {
        int nz = 0;
        #pragma unroll 8
        for (int k = 0; k < 256; k++) nz += (ei[2 * k + 1] != 0);
        g_is64 = (nz < 16) ? 1 : 0;
    }
}

// ---------------- fragment address setup (shared by edge + gemm) ----------------
__device__ __forceinline__ void frag_addrs(unsigned as_b, unsigned bs_b, int lane,
                                           int wm, int wn, unsigned* aa, unsigned* bb) {
    int g = lane >> 3, sub = lane & 7;
    #pragma unroll
    for (int mi = 0; mi < 2; mi++)
        aa[mi] = as_b + (((wm * 32 + mi * 16 + (g & 1) * 8 + sub) * 36 + (g >> 1) * 4) << 2);
    #pragma unroll
    for (int j = 0; j < 4; j++)
        bb[j] = bs_b + (((wn * 64 + (2 * j + (g >> 1)) * 8 + sub) * 36 + (g & 1) * 4) << 2);
}

// ---------------- edge phase: tf32 MMA (ldmatrix) + fused gather/relu/scatter ----------------
__global__ void __launch_bounds__(256) edge_tf32(
    const float* __restrict__ eattr, const void* __restrict__ ei,
    const float* __restrict__ x, const float* __restrict__ be, int E)
{
    __shared__ GemmSM sm;
    __shared__ int s_src[128], s_dst[128];

    const int tid = threadIdx.x;
    const int lane = tid & 31, warp = tid >> 5;
    const int wm = warp & 3, wn = warp >> 2;
    const int r0 = lane >> 2, c0 = lane & 3;
    const int eb = blockIdx.x * 128;
    const int is64 = g_is64;
    const unsigned* Wt = g_wt + WE_T_OFF;

    unsigned as_b = (unsigned)__cvta_generic_to_shared(&sm.ab.As[0]);
    unsigned bs_b = (unsigned)__cvta_generic_to_shared(&sm.ab.Bst[0]);
    unsigned aa[2], bb[4];
    frag_addrs(as_b, bs_b, lane, wm, wn, aa, bb);

    if (tid < 128) {
        int eg = eb + tid;
        if (eg < E) {
            s_src[tid] = (int)load_index(ei, eg, is64);
            s_dst[tid] = (int)load_index(ei, (long)E + eg, is64);
        } else { s_src[tid] = 0; s_dst[tid] = 0; }
    }

    float acc[2][8][4];
    #pragma unroll
    for (int mi = 0; mi < 2; mi++)
        #pragma unroll
        for (int ni = 0; ni < 8; ni++)
            #pragma unroll
            for (int q = 0; q < 4; q++) acc[mi][ni][q] = 0.f;

    #pragma unroll
    for (int k0 = 0; k0 < ED_CH; k0 += 32) {
        #pragma unroll
        for (int i = 0; i < 4; i++) {   // B: We_t (128n x 32k) via cp.async
            int f = tid + i * 256;
            int n = f >> 3, kk = (f & 7) * 4;
            cpasync16(bs_b + ((n * 36 + kk) << 2), &Wt[(size_t)n * ED_CH + k0 + kk]);
        }
        float4 av[4];
        #pragma unroll
        for (int i = 0; i < 4; i++) {   // A: edge_attr (128 x 32)
            int f = tid + i * 256;
            int row = f >> 3, kk = (f & 7) * 4;
            int eg = eb + row;
            av[i] = (eg < E) ? *(const float4*)&eattr[(size_t)eg * ED_CH + k0 + kk]
                             : make_float4(0.f, 0.f, 0.f, 0.f);
        }
        #pragma unroll
        for (int i = 0; i < 4; i++) {
            int f = tid + i * 256;
            int row = f >> 3, kk = (f & 7) * 4;
            unsigned* p = &sm.ab.As[row * 36 + kk];
            p[0] = f2tf(av[i].x); p[1] = f2tf(av[i].y);
            p[2] = f2tf(av[i].z); p[3] = f2tf(av[i].w);
        }
        cp_commit_wait();
        __syncthreads();
        #pragma unroll
        for (int ks = 0; ks < 4; ks++) {
            unsigned a[2][4], b[4][4];
            ldsm4(a[0], aa[0] + ks * 32);
            ldsm4(a[1], aa[1] + ks * 32);
            #pragma unroll
            for (int j = 0; j < 4; j++) ldsm4(b[j], bb[j] + ks * 32);
            #pragma unroll
            for (int mi = 0; mi < 2; mi++)
                #pragma unroll
                for (int ni = 0; ni < 8; ni++)
                    mma8(acc[mi][ni], a[mi], &b[ni >> 1][(ni & 1) * 2]);
        }
        __syncthreads();
    }

    const float4 bev = *(const float4*)&be[lane * 4];

    // epilogue in 2 phases of 64 edge-rows (Cs overlays As/Bst)
    #pragma unroll
    for (int p = 0; p < 2; p++) {
        if ((wm >> 1) == p) {
            #pragma unroll
            for (int mi = 0; mi < 2; mi++)
                #pragma unroll
                for (int ni = 0; ni < 8; ni++) {
                    int r = (wm & 1) * 32 + mi * 16 + r0;
                    int col = wn * 64 + ni * 8 + 2 * c0;
                    sm.Cs[r * 132 + col]           = acc[mi][ni][0];
                    sm.Cs[r * 132 + col + 1]       = acc[mi][ni][1];
                    sm.Cs[(r + 8) * 132 + col]     = acc[mi][ni][2];
                    sm.Cs[(r + 8) * 132 + col + 1] = acc[mi][ni][3];
                }
        }
        __syncthreads();
        #pragma unroll
        for (int half = 0; half < 2; half++) {
            float4 cv[4], xv[4];
            int dd[4], ok[4];
            #pragma unroll
            for (int j = 0; j < 4; j++) {
                int el = warp * 8 + half * 4 + j;
                int eg = eb + p * 64 + el;
                ok[j] = (eg < E);
                int s = s_src[p * 64 + el];
                dd[j] = s_dst[p * 64 + el];
                cv[j] = *(const float4*)&sm.Cs[el * 132 + lane * 4];
                xv[j] = ok[j] ? *(const float4*)&x[(size_t)s * IN_CH + lane * 4]
                              : make_float4(0.f, 0.f, 0.f, 0.f);
            }
            #pragma unroll
            for (int j = 0; j < 4; j++) {
                if (ok[j]) {
                    red4(&g_agg[(size_t)dd[j] * IN_CH + lane * 4],
                         fmaxf(cv[j].x + bev.x + xv[j].x, 0.f),
                         fmaxf(cv[j].y + bev.y + xv[j].y, 0.f),
                         fmaxf(cv[j].z + bev.z + xv[j].z, 0.f),
                         fmaxf(cv[j].w + bev.w + xv[j].w, 0.f));
                }
            }
        }
        __syncthreads();
    }
}

// ---------------- tf32 tensor-core GEMM for node MLPs ----------------
// MODE 0: t  = relu(h  @ W1  + b1)   K=128 N=256   (h == g_agg)
// MODE 1: h2 =      t  @ W2  + b2    K=256 N=256
// MODE 2: gate = relu(h2 @ Wg1 + bg1) @ Wg2 + bg2  K=256 N=128 (fused, writes g_gate only)
template <int MODE>
__global__ void __launch_bounds__(256) gemm_tf32(const float* __restrict__ bias,
                                                 const float* __restrict__ Wg2,
                                                 const float* __restrict__ bg2, int M)
{
    constexpr int K = (MODE == 0) ? 128 : 256;
    constexpr int N = (MODE == 2) ? 128 : 256;
    const float* __restrict__ A = (MODE == 0) ? g_agg : (MODE == 1) ? g_t : g_h2;
    float* __restrict__ C       = (MODE == 0) ? g_t : g_h2;   // unused for MODE 2
    const unsigned* Wt = g_wt + ((MODE == 0) ? W1_T_OFF : (MODE == 1) ? W2_T_OFF : WG1_T_OFF);

    __shared__ GemmSM sm;

    const int tid = threadIdx.x;
    const int lane = tid & 31, warp = tid >> 5;
    const int wm = warp & 3, wn = warp >> 2;
    const int r0 = lane >> 2, c0 = lane & 3;
    const int bm = blockIdx.y * 128, bn = blockIdx.x * 128;

    unsigned as_b = (unsigned)__cvta_generic_to_shared(&sm.ab.As[0]);
    unsigned bs_b = (unsigned)__cvta_generic_to_shared(&sm.ab.Bst[0]);
    unsigned aa[2], bb[4];
    frag_addrs(as_b, bs_b, lane, wm, wn, aa, bb);

    float acc[2][8][4];
    #pragma unroll
    for (int mi = 0; mi < 2; mi++)
        #pragma unroll
        for (int ni = 0; ni < 8; ni++)
            #pragma unroll
            for (int q = 0; q < 4; q++) acc[mi][ni][q] = 0.f;

    for (int k0 = 0; k0 < K; k0 += 32) {
        #pragma unroll
        for (int i = 0; i < 4; i++) {
            int f = tid + i * 256;
            int n = f >> 3, kk = (f & 7) * 4;
            cpasync16(bs_b + ((n * 36 + kk) << 2), &Wt[(size_t)(bn + n) * K + k0 + kk]);
        }
        float4 av[4];
        #pragma unroll
        for (int i = 0; i < 4; i++) {
            int f = tid + i * 256;
            int row = f >> 3, kk = (f & 7) * 4;
            int gm = bm + row;
            av[i] = (gm < M) ? *(const float4*)&A[(size_t)gm * K + k0 + kk]
                             : make_float4(0.f, 0.f, 0.f, 0.f);
        }
        #pragma unroll
        for (int i = 0; i < 4; i++) {
            int f = tid + i * 256;
            int row = f >> 3, kk = (f & 7) * 4;
            unsigned* p = &sm.ab.As[row * 36 + kk];
            p[0] = f2tf(av[i].x); p[1] = f2tf(av[i].y);
            p[2] = f2tf(av[i].z); p[3] = f2tf(av[i].w);
        }
        cp_commit_wait();
        __syncthreads();
        #pragma unroll
        for (int ks = 0; ks < 4; ks++) {
            unsigned a[2][4], b[4][4];
            ldsm4(a[0], aa[0] + ks * 32);
            ldsm4(a[1], aa[1] + ks * 32);
            #pragma unroll
            for (int j = 0; j < 4; j++) ldsm4(b[j], bb[j] + ks * 32);
            #pragma unroll
            for (int mi = 0; mi < 2; mi++)
                #pragma unroll
                for (int ni = 0; ni < 8; ni++)
                    mma8(acc[mi][ni], a[mi], &b[ni >> 1][(ni & 1) * 2]);
        }
        __syncthreads();
    }

    if constexpr (MODE != 2) {
        constexpr bool RELU = (MODE == 0);
        #pragma unroll
        for (int mi = 0; mi < 2; mi++) {
            #pragma unroll
            for (int ni = 0; ni < 8; ni++) {
                int row = bm + wm * 32 + mi * 16 + r0;
                int col = bn + wn * 64 + ni * 8 + 2 * c0;
                float bx = bias[col], by = bias[col + 1];
                float v0 = acc[mi][ni][0] + bx, v1 = acc[mi][ni][1] + by;
                float v2 = acc[mi][ni][2] + bx, v3 = acc[mi][ni][3] + by;
                if (RELU) {
                    v0 = fmaxf(v0, 0.f); v1 = fmaxf(v1, 0.f);
                    v2 = fmaxf(v2, 0.f); v3 = fmaxf(v3, 0.f);
                }
                if (row < M)     *(float2*)&C[(size_t)row * N + col]       = make_float2(v0, v1);
                if (row + 8 < M) *(float2*)&C[(size_t)(row + 8) * N + col] = make_float2(v2, v3);
            }
        }
    } else {
        // fused gate: g1 tile (128 x 128) -> smem in 2 phases, warp-per-row dot with Wg2
        const float4 wgv = *(const float4*)&Wg2[lane * 4];
        const float bg2v = bg2[0];
        #pragma unroll
        for (int p = 0; p < 2; p++) {
            if ((wm >> 1) == p) {
                #pragma unroll
                for (int mi = 0; mi < 2; mi++)
                    #pragma unroll
                    for (int ni = 0; ni < 8; ni++) {
                        int r = (wm & 1) * 32 + mi * 16 + r0;
                        int col = wn * 64 + ni * 8 + 2 * c0;
                        float bx = bias[col], by = bias[col + 1];
                        sm.Cs[r * 132 + col]           = fmaxf(acc[mi][ni][0] + bx, 0.f);
                        sm.Cs[r * 132 + col + 1]       = fmaxf(acc[mi][ni][1] + by, 0.f);
                        sm.Cs[(r + 8) * 132 + col]     = fmaxf(acc[mi][ni][2] + bx, 0.f);
                        sm.Cs[(r + 8) * 132 + col + 1] = fmaxf(acc[mi][ni][3] + by, 0.f);
                    }
            }
            __syncthreads();
            #pragma unroll 2
            for (int j = 0; j < 8; j++) {
                int el = warp * 8 + j;
                int row = bm + p * 64 + el;
                if (row < M) {
                    float4 cvv = *(const float4*)&sm.Cs[el * 132 + lane * 4];
                    float s = cvv.x * wgv.x + cvv.y * wgv.y + cvv.z * wgv.z + cvv.w * wgv.w;
                    #pragma unroll
                    for (int o = 16; o; o >>= 1) s += __shfl_xor_sync(0xffffffffu, s, o);
                    if (lane == 0) g_gate[row] = s + bg2v;
                }
            }
            __syncthreads();
        }
    }
}

// ---------------- per-graph max of gate ----------------
__global__ void gmax_kernel(const void* __restrict__ batch, int n) {
    int i = blockIdx.x * blockDim.x + threadIdx.x;
    if (i >= n) return;
    int b = (int)load_index(batch, i, g_is64);
    atomicMax(&g_gmax[b], fenc(g_gate[i]));
}

// ---------------- softmax numerator + weighted sum: warp strips with run-length flush ----------------
__global__ void gsum_kernel(const void* __restrict__ batch, int n) {
    int w = (blockIdx.x * blockDim.x + threadIdx.x) >> 5;
    int lane = threadIdx.x & 31;
    int W = (gridDim.x * blockDim.x) >> 5;
    int L = (n + W - 1) / W;
    int s0 = w * L, e0 = min(s0 + L, n);
    if (s0 >= e0) return;
    const int is64 = g_is64;

    int bcur = (int)load_index(batch, s0, is64);
    float r[8];
    #pragma unroll
    for (int q = 0; q < 8; q++) r[q] = 0.f;
    float dsum = 0.f;

    for (int i = s0; i < e0; i++) {
        int b = (int)load_index(batch, i, is64);
        if (b != bcur) {
            float* pr = &g_pnum[bcur * HID_CH + lane * 8];
            red4(pr, r[0], r[1], r[2], r[3]);
            red4(pr + 4, r[4], r[5], r[6], r[7]);
            if (lane == 0) atomicAdd(&g_denom[bcur], dsum);
            #pragma unroll
            for (int q = 0; q < 8; q++) r[q] = 0.f;
            dsum = 0.f;
            bcur = b;
        }
        float a = expf(g_gate[i] - fdec(g_gmax[b]));
        const float* hr = &g_h2[(size_t)i * HID_CH + lane * 8];
        float4 h0 = *(const float4*)hr;
        float4 h1 = *(const float4*)(hr + 4);
        r[0] += a * h0.x; r[1] += a * h0.y; r[2] += a * h0.z; r[3] += a * h0.w;
        r[4] += a * h1.x; r[5] += a * h1.y; r[6] += a * h1.z; r[7] += a * h1.w;
        dsum += a;
    }
    float* pr = &g_pnum[bcur * HID_CH + lane * 8];
    red4(pr, r[0], r[1], r[2], r[3]);
    red4(pr + 4, r[4], r[5], r[6], r[7]);
    if (lane == 0) atomicAdd(&g_denom[bcur], dsum);
}

// ---------------- pooled = pnum / denom; write to output tail ----------------
__global__ void pool_kernel(float* __restrict__ out, int B) {
    int i = blockIdx.x * blockDim.x + threadIdx.x;
    if (i >= B * HID_CH) return;
    int b = i >> 8;
    float d = g_denom[b];
    float p = (d > 0.f) ? g_pnum[i] / d : 0.f;
    g_pooled[i] = p;
    out[(size_t)B * K_CLS + i] = p;
}

// ---------------- logits = pooled @ Wh + bh  (8 graphs per block, Wh reused 8x) ----------------
__global__ void __launch_bounds__(128) head_kernel(const float* __restrict__ Wh,
                                                   const float* __restrict__ bh,
                                                   float* __restrict__ out, int B) {
    __shared__ float p[8][HID_CH];   // 8 KB
    int kb = blockIdx.x * 128 + threadIdx.x;
    int b0 = blockIdx.y * 8;
    int nb = min(8, B - b0);
    for (int i = threadIdx.x; i < nb * HID_CH; i += 128)
        p[i >> 8][i & 255] = g_pooled[(b0 + (i >> 8)) * HID_CH + (i & 255)];
    __syncthreads();
    if (kb >= K_CLS) return;
    float acc[8];
    #pragma unroll
    for (int j = 0; j < 8; j++) acc[j] = 0.f;
    #pragma unroll 4
    for (int c = 0; c < HID_CH; c++) {
        float wv = Wh[(size_t)c * K_CLS + kb];
        #pragma unroll
        for (int j = 0; j < 8; j++) acc[j] += p[j][c] * wv;
    }
    float bv = bh[kb];
    for (int j = 0; j < nb; j++)
        out[(size_t)(b0 + j) * K_CLS + kb] = acc[j] + bv;
}

// ---------------- launch ----------------
extern "C" void kernel_launch(void* const* d_in, const int* in_sizes, int n_in,
                              void* d_out, int out_size) {
    const float* x     = (const float*)d_in[0];
    const void*  ei    = d_in[1];
    const float* eattr = (const float*)d_in[2];
    const void*  batch = d_in[3];
    const float* We    = (const float*)d_in[4];
    const float* be    = (const float*)d_in[5];
    const float* W1    = (const float*)d_in[6];
    const float* b1    = (const float*)d_in[7];
    const float* W2    = (const float*)d_in[8];
    const float* b2    = (const float*)d_in[9];
    const float* Wg1   = (const float*)d_in[10];
    const float* bg1   = (const float*)d_in[11];
    const float* Wg2   = (const float*)d_in[12];
    const float* bg2   = (const float*)d_in[13];
    const float* Wh    = (const float*)d_in[14];
    const float* bh    = (const float*)d_in[15];
    float* out = (float*)d_out;

    int n = in_sizes[0] / IN_CH;
    int E = in_sizes[2] / ED_CH;
    int B = out_size / (K_CLS + HID_CH);

    dim3 pb(32, 8);
    prep_kernel<<<dim3(IN_CH / 32, ED_CH / 32), pb>>>(We, ED_CH, IN_CH, WE_T_OFF);
    prep_kernel<<<dim3(HID_CH / 32, IN_CH / 32), pb>>>(W1, IN_CH, HID_CH, W1_T_OFF);
    prep_kernel<<<dim3(HID_CH / 32, HID_CH / 32), pb>>>(W2, HID_CH, HID_CH, W2_T_OFF);
    prep_kernel<<<dim3(128 / 32, HID_CH / 32), pb>>>(Wg1, HID_CH, 128, WG1_T_OFF);
    init_kernel<<<2048, 256>>>(x, (const int*)ei, n);

    edge_tf32<<<(E + 127) / 128, 256>>>(eattr, ei, x, be, E);

    int mb = (n + 127) / 128;
    gemm_tf32<0><<<dim3(2, mb), 256>>>(b1, nullptr, nullptr, n);
    gemm_tf32<1><<<dim3(2, mb), 256>>>(b2, nullptr, nullptr, n);
    gemm_tf32<2><<<dim3(1, mb), 256>>>(bg1, Wg2, bg2, n);

    gmax_kernel<<<(n + 255) / 256, 256>>>(batch, n);
    gsum_kernel<<<400, 256>>>(batch, n);
    pool_kernel<<<(B * HID_CH + 255) / 256, 256>>>(out, B);
    head_kernel<<<dim3(8, (B + 7) / 8), 128>>>(Wh, bh, out, B);
}

// round 5
// speedup vs baseline: 2.7201x; 1.1965x over previous
#include <cuda_runtime.h>
#include <cuda_fp16.h>
#include <math.h>

#define IN_CH  128
#define ED_CH  64
#define HID_CH 256
#define K_CLS  1000
#define MAXN   50000
#define MAXB   128

// transposed fp16 weights: [n][k] layouts (offsets in half elements)
#define WE_T_OFF  0          // 128 x 64
#define W1_T_OFF  8192       // 256 x 128
#define W2_T_OFF  40960      // 256 x 256
#define WG1_T_OFF 106496     // 128 x 256

// ---------------- scratch (static device globals; no allocation) ----------------
__device__ float    g_agg[MAXN * IN_CH];     // init = x, edge adds messages -> becomes h
__device__ float    g_t[MAXN * HID_CH];
__device__ float    g_h2[MAXN * HID_CH];
__device__ float    g_gate[MAXN];
__device__ unsigned g_gmax[MAXB];
__device__ float    g_denom[MAXB];
__device__ float    g_pnum[MAXB * HID_CH];
__device__ float    g_pooled[MAXB * HID_CH];
__device__ __half   g_wt[139264];
__device__ int      g_is64;

// ---------------- helpers ----------------
__device__ __forceinline__ unsigned fenc(float f) {
    unsigned u = __float_as_uint(f);
    return (u & 0x80000000u) ? ~u : (u | 0x80000000u);
}
__device__ __forceinline__ float fdec(unsigned u) {
    return __uint_as_float((u & 0x80000000u) ? (u ^ 0x80000000u) : ~u);
}
__device__ __forceinline__ void red4(float* p, float a, float b, float c, float d) {
    asm volatile("red.global.add.v4.f32 [%0], {%1,%2,%3,%4};"
                 :: "l"(p), "f"(a), "f"(b), "f"(c), "f"(d) : "memory");
}
__device__ __forceinline__ long long load_index(const void* p, long i, int is64) {
    if (is64) return ((const long long*)p)[i];
    return (long long)((const int*)p)[i];
}
__device__ __forceinline__ unsigned f2h2(float a, float b) {
    __half2 h = __floats2half2_rn(a, b);
    return *(unsigned*)&h;
}
__device__ __forceinline__ void mma16(float* c, const unsigned* a, const unsigned* b) {
    asm volatile("mma.sync.aligned.m16n8k16.row.col.f32.f16.f16.f32 "
                 "{%0,%1,%2,%3}, {%4,%5,%6,%7}, {%8,%9}, {%0,%1,%2,%3};"
                 : "+f"(c[0]), "+f"(c[1]), "+f"(c[2]), "+f"(c[3])
                 : "r"(a[0]), "r"(a[1]), "r"(a[2]), "r"(a[3]), "r"(b[0]), "r"(b[1]));
}
__device__ __forceinline__ void ldsm4(unsigned* r, unsigned addr) {
    asm volatile("ldmatrix.sync.aligned.m8n8.x4.shared.b16 {%0,%1,%2,%3}, [%4];"
                 : "=r"(r[0]), "=r"(r[1]), "=r"(r[2]), "=r"(r[3]) : "r"(addr));
}
__device__ __forceinline__ void cpasync16(unsigned saddr, const void* g) {
    asm volatile("cp.async.cg.shared.global [%0], [%1], 16;" :: "r"(saddr), "l"(g) : "memory");
}
__device__ __forceinline__ void cp_commit_wait() {
    asm volatile("cp.async.commit_group;\ncp.async.wait_group 0;" ::: "memory");
}

// smem union: fp16 mainloop tiles (row stride 72 halves = conflict-free ldsm) overlay C tile
union GemmSM {
    struct { __half As[128 * 72]; __half Bst[128 * 72]; } ab;   // 18KB + 18KB
    float Cs[64 * 132];                                          // 33.8KB
};

// fragment smem byte-addresses for ldmatrix (A: [m][k] rows, B: [n][k] rows)
__device__ __forceinline__ void frag_addrs(unsigned as_b, unsigned bs_b, int lane,
                                           int wm, int wn, unsigned* aa, unsigned* bb) {
    #pragma unroll
    for (int mi = 0; mi < 2; mi++)
        aa[mi] = as_b + ((wm * 32 + mi * 16 + (lane & 15)) * 72 + (lane >> 4) * 8) * 2;
    #pragma unroll
    for (int nj = 0; nj < 4; nj++)
        bb[nj] = bs_b + ((wn * 64 + nj * 16 + (lane & 7) + ((lane >> 4) & 1) * 8) * 72
                         + ((lane >> 3) & 1) * 8) * 2;
}

// ---------------- weight prep: Wt16[n][k] = half(W[k][n]); all 4 weights in one launch ----------------
__global__ void prep_kernel(const float* __restrict__ We, const float* __restrict__ W1,
                            const float* __restrict__ W2, const float* __restrict__ Wg1) {
    __shared__ float t[32][33];
    const float* W; int K, N, off;
    switch (blockIdx.z) {
        case 0: W = We;  K = ED_CH;  N = IN_CH;  off = WE_T_OFF;  break;
        case 1: W = W1;  K = IN_CH;  N = HID_CH; off = W1_T_OFF;  break;
        case 2: W = W2;  K = HID_CH; N = HID_CH; off = W2_T_OFF;  break;
        default:W = Wg1; K = HID_CH; N = 128;    off = WG1_T_OFF; break;
    }
    int n0 = blockIdx.x * 32, k0 = blockIdx.y * 32;
    if (n0 >= N || k0 >= K) return;
    __half* dst = g_wt + off;
    for (int i = threadIdx.y; i < 32; i += 8)
        t[i][threadIdx.x] = W[(size_t)(k0 + i) * N + n0 + threadIdx.x];
    __syncthreads();
    for (int i = threadIdx.y; i < 32; i += 8)
        dst[(size_t)(n0 + i) * K + k0 + threadIdx.x] = __float2half(t[threadIdx.x][i]);
}

// ---------------- init: g_agg = x, zero pool accumulators, sniff index dtype ----------------
__global__ void init_kernel(const float* __restrict__ x, const int* __restrict__ ei, int n) {
    int stride = gridDim.x * blockDim.x;
    int i = blockIdx.x * blockDim.x + threadIdx.x;
    int n4 = n * IN_CH / 4;
    for (int j = i; j < n4; j += stride) ((float4*)g_agg)[j] = ((const float4*)x)[j];
    if (i < MAXB * HID_CH) g_pnum[i] = 0.f;
    if (i < MAXB) { g_denom[i] = 0.f; g_gmax[i] = 0u; }
    if (i == 0) {
        int nz = 0;
        #pragma unroll 8
        for (int k = 0; k < 256; k++) nz += (ei[2 * k + 1] != 0);
        g_is64 = (nz < 16) ? 1 : 0;
    }
}

// ---------------- edge phase: fp16 MMA (K=64, single chunk) + fused gather/relu/scatter ----------------
__global__ void __launch_bounds__(256) edge_mma(
    const float* __restrict__ eattr, const void* __restrict__ ei,
    const float* __restrict__ x, const float* __restrict__ be, int E)
{
    __shared__ GemmSM sm;
    __shared__ int s_src[128], s_dst[128];

    const int tid = threadIdx.x;
    const int lane = tid & 31, warp = tid >> 5;
    const int wm = warp & 3, wn = warp >> 2;
    const int r0 = lane >> 2, c0 = lane & 3;
    const int eb = blockIdx.x * 128;
    const int is64 = g_is64;
    const __half* Wt = g_wt + WE_T_OFF;

    unsigned as_b = (unsigned)__cvta_generic_to_shared(&sm.ab.As[0]);
    unsigned bs_b = (unsigned)__cvta_generic_to_shared(&sm.ab.Bst[0]);
    unsigned aa[2], bb[4];
    frag_addrs(as_b, bs_b, lane, wm, wn, aa, bb);

    // B: We_t (128n x 64k halves) via cp.async, full K
    #pragma unroll
    for (int i = 0; i < 4; i++) {
        int f = tid + i * 256;
        int n = f >> 3, kk = (f & 7) * 8;
        cpasync16(bs_b + (n * 72 + kk) * 2, &Wt[(size_t)n * ED_CH + kk]);
    }

    if (tid < 128) {
        int eg = eb + tid;
        if (eg < E) {
            s_src[tid] = (int)load_index(ei, eg, is64);
            s_dst[tid] = (int)load_index(ei, (long)E + eg, is64);
        } else { s_src[tid] = 0; s_dst[tid] = 0; }
    }

    // A: edge_attr (128 x 64), load f32, convert to half in smem
    #pragma unroll
    for (int i = 0; i < 4; i++) {
        int f = tid + i * 256;
        int row = f >> 3, kk = (f & 7) * 8;
        int eg = eb + row;
        float4 v0 = make_float4(0.f, 0.f, 0.f, 0.f), v1 = v0;
        if (eg < E) {
            v0 = *(const float4*)&eattr[(size_t)eg * ED_CH + kk];
            v1 = *(const float4*)&eattr[(size_t)eg * ED_CH + kk + 4];
        }
        uint4 h;
        h.x = f2h2(v0.x, v0.y); h.y = f2h2(v0.z, v0.w);
        h.z = f2h2(v1.x, v1.y); h.w = f2h2(v1.z, v1.w);
        *(uint4*)&sm.ab.As[row * 72 + kk] = h;
    }
    cp_commit_wait();
    __syncthreads();

    float acc[2][8][4];
    #pragma unroll
    for (int mi = 0; mi < 2; mi++)
        #pragma unroll
        for (int ni = 0; ni < 8; ni++)
            #pragma unroll
            for (int q = 0; q < 4; q++) acc[mi][ni][q] = 0.f;

    #pragma unroll
    for (int ks = 0; ks < 4; ks++) {
        unsigned a[2][4], b[4][4];
        ldsm4(a[0], aa[0] + ks * 32);
        ldsm4(a[1], aa[1] + ks * 32);
        #pragma unroll
        for (int j = 0; j < 4; j++) ldsm4(b[j], bb[j] + ks * 32);
        #pragma unroll
        for (int mi = 0; mi < 2; mi++)
            #pragma unroll
            for (int ni = 0; ni < 8; ni++)
                mma16(acc[mi][ni], a[mi], &b[ni >> 1][(ni & 1) * 2]);
    }
    __syncthreads();

    const float4 bev = *(const float4*)&be[lane * 4];

    // epilogue in 2 phases of 64 edge-rows (Cs overlays As/Bst)
    #pragma unroll
    for (int p = 0; p < 2; p++) {
        if ((wm >> 1) == p) {
            #pragma unroll
            for (int mi = 0; mi < 2; mi++)
                #pragma unroll
                for (int ni = 0; ni < 8; ni++) {
                    int r = (wm & 1) * 32 + mi * 16 + r0;
                    int col = wn * 64 + ni * 8 + 2 * c0;
                    sm.Cs[r * 132 + col]           = acc[mi][ni][0];
                    sm.Cs[r * 132 + col + 1]       = acc[mi][ni][1];
                    sm.Cs[(r + 8) * 132 + col]     = acc[mi][ni][2];
                    sm.Cs[(r + 8) * 132 + col + 1] = acc[mi][ni][3];
                }
        }
        __syncthreads();
        #pragma unroll
        for (int half = 0; half < 2; half++) {
            float4 cv[4], xv[4];
            int dd[4], ok[4];
            #pragma unroll
            for (int j = 0; j < 4; j++) {
                int el = warp * 8 + half * 4 + j;
                int eg = eb + p * 64 + el;
                ok[j] = (eg < E);
                int s = s_src[p * 64 + el];
                dd[j] = s_dst[p * 64 + el];
                cv[j] = *(const float4*)&sm.Cs[el * 132 + lane * 4];
                xv[j] = ok[j] ? *(const float4*)&x[(size_t)s * IN_CH + lane * 4]
                              : make_float4(0.f, 0.f, 0.f, 0.f);
            }
            #pragma unroll
            for (int j = 0; j < 4; j++) {
                if (ok[j]) {
                    red4(&g_agg[(size_t)dd[j] * IN_CH + lane * 4],
                         fmaxf(cv[j].x + bev.x + xv[j].x, 0.f),
                         fmaxf(cv[j].y + bev.y + xv[j].y, 0.f),
                         fmaxf(cv[j].z + bev.z + xv[j].z, 0.f),
                         fmaxf(cv[j].w + bev.w + xv[j].w, 0.f));
                }
            }
        }
        __syncthreads();
    }
}

// ---------------- fp16 tensor-core GEMM for node MLPs ----------------
// MODE 0: t  = relu(h  @ W1  + b1)   K=128 N=256   (h == g_agg)
// MODE 1: h2 =      t  @ W2  + b2    K=256 N=256
// MODE 2: gate = relu(h2 @ Wg1 + bg1) @ Wg2 + bg2  K=256 N=128 (fused; writes g_gate + gmax)
template <int MODE>
__global__ void __launch_bounds__(256) gemm_mma(const float* __restrict__ bias,
                                                const float* __restrict__ Wg2,
                                                const float* __restrict__ bg2,
                                                const void* __restrict__ batch, int M)
{
    constexpr int K = (MODE == 0) ? 128 : 256;
    constexpr int N = (MODE == 2) ? 128 : 256;
    const float* __restrict__ A = (MODE == 0) ? g_agg : (MODE == 1) ? g_t : g_h2;
    float* __restrict__ C       = (MODE == 0) ? g_t : g_h2;   // unused for MODE 2
    const __half* Wt = g_wt + ((MODE == 0) ? W1_T_OFF : (MODE == 1) ? W2_T_OFF : WG1_T_OFF);

    __shared__ GemmSM sm;

    const int tid = threadIdx.x;
    const int lane = tid & 31, warp = tid >> 5;
    const int wm = warp & 3, wn = warp >> 2;
    const int r0 = lane >> 2, c0 = lane & 3;
    const int bm = blockIdx.y * 128, bn = blockIdx.x * 128;

    unsigned as_b = (unsigned)__cvta_generic_to_shared(&sm.ab.As[0]);
    unsigned bs_b = (unsigned)__cvta_generic_to_shared(&sm.ab.Bst[0]);
    unsigned aa[2], bb[4];
    frag_addrs(as_b, bs_b, lane, wm, wn, aa, bb);

    float acc[2][8][4];
    #pragma unroll
    for (int mi = 0; mi < 2; mi++)
        #pragma unroll
        for (int ni = 0; ni < 8; ni++)
            #pragma unroll
            for (int q = 0; q < 4; q++) acc[mi][ni][q] = 0.f;

    for (int k0 = 0; k0 < K; k0 += 64) {
        #pragma unroll
        for (int i = 0; i < 4; i++) {   // B chunk via cp.async (pre-converted halves)
            int f = tid + i * 256;
            int n = f >> 3, kk = (f & 7) * 8;
            cpasync16(bs_b + (n * 72 + kk) * 2, &Wt[(size_t)(bn + n) * K + k0 + kk]);
        }
        #pragma unroll
        for (int i = 0; i < 4; i++) {   // A chunk: f32 -> half2 into smem
            int f = tid + i * 256;
            int row = f >> 3, kk = (f & 7) * 8;
            int gm = bm + row;
            float4 v0 = make_float4(0.f, 0.f, 0.f, 0.f), v1 = v0;
            if (gm < M) {
                v0 = *(const float4*)&A[(size_t)gm * K + k0 + kk];
                v1 = *(const float4*)&A[(size_t)gm * K + k0 + kk + 4];
            }
            uint4 h;
            h.x = f2h2(v0.x, v0.y); h.y = f2h2(v0.z, v0.w);
            h.z = f2h2(v1.x, v1.y); h.w = f2h2(v1.z, v1.w);
            *(uint4*)&sm.ab.As[row * 72 + kk] = h;
        }
        cp_commit_wait();
        __syncthreads();
        #pragma unroll
        for (int ks = 0; ks < 4; ks++) {
            unsigned a[2][4], b[4][4];
            ldsm4(a[0], aa[0] + ks * 32);
            ldsm4(a[1], aa[1] + ks * 32);
            #pragma unroll
            for (int j = 0; j < 4; j++) ldsm4(b[j], bb[j] + ks * 32);
            #pragma unroll
            for (int mi = 0; mi < 2; mi++)
                #pragma unroll
                for (int ni = 0; ni < 8; ni++)
                    mma16(acc[mi][ni], a[mi], &b[ni >> 1][(ni & 1) * 2]);
        }
        __syncthreads();
    }

    if constexpr (MODE != 2) {
        constexpr bool RELU = (MODE == 0);
        #pragma unroll
        for (int mi = 0; mi < 2; mi++) {
            #pragma unroll
            for (int ni = 0; ni < 8; ni++) {
                int row = bm + wm * 32 + mi * 16 + r0;
                int col = bn + wn * 64 + ni * 8 + 2 * c0;
                float bx = bias[col], by = bias[col + 1];
                float v0 = acc[mi][ni][0] + bx, v1 = acc[mi][ni][1] + by;
                float v2 = acc[mi][ni][2] + bx, v3 = acc[mi][ni][3] + by;
                if (RELU) {
                    v0 = fmaxf(v0, 0.f); v1 = fmaxf(v1, 0.f);
                    v2 = fmaxf(v2, 0.f); v3 = fmaxf(v3, 0.f);
                }
                if (row < M)     *(float2*)&C[(size_t)row * N + col]       = make_float2(v0, v1);
                if (row + 8 < M) *(float2*)&C[(size_t)(row + 8) * N + col] = make_float2(v2, v3);
            }
        }
    } else {
        // fused gate: g1 tile (128 x 128) -> smem in 2 phases, warp-per-row dot with Wg2,
        // then gate write + per-graph atomicMax
        const float4 wgv = *(const float4*)&Wg2[lane * 4];
        const float bg2v = bg2[0];
        const int is64 = g_is64;
        #pragma unroll
        for (int p = 0; p < 2; p++) {
            if ((wm >> 1) == p) {
                #pragma unroll
                for (int mi = 0; mi < 2; mi++)
                    #pragma unroll
                    for (int ni = 0; ni < 8; ni++) {
                        int r = (wm & 1) * 32 + mi * 16 + r0;
                        int col = wn * 64 + ni * 8 + 2 * c0;
                        float bx = bias[col], by = bias[col + 1];
                        sm.Cs[r * 132 + col]           = fmaxf(acc[mi][ni][0] + bx, 0.f);
                        sm.Cs[r * 132 + col + 1]       = fmaxf(acc[mi][ni][1] + by, 0.f);
                        sm.Cs[(r + 8) * 132 + col]     = fmaxf(acc[mi][ni][2] + bx, 0.f);
                        sm.Cs[(r + 8) * 132 + col + 1] = fmaxf(acc[mi][ni][3] + by, 0.f);
                    }
            }
            __syncthreads();
            #pragma unroll 2
            for (int j = 0; j < 8; j++) {
                int el = warp * 8 + j;
                int row = bm + p * 64 + el;
                if (row < M) {
                    float4 cvv = *(const float4*)&sm.Cs[el * 132 + lane * 4];
                    float s = cvv.x * wgv.x + cvv.y * wgv.y + cvv.z * wgv.z + cvv.w * wgv.w;
                    #pragma unroll
                    for (int o = 16; o; o >>= 1) s += __shfl_xor_sync(0xffffffffu, s, o);
                    if (lane == 0) {
                        float g = s + bg2v;
                        g_gate[row] = g;
                        int b = (int)load_index(batch, row, is64);
                        atomicMax(&g_gmax[b], fenc(g));
                    }
                }
            }
            __syncthreads();
        }
    }
}

// ---------------- softmax numerator + weighted sum: warp strips with run-length flush ----------------
__global__ void gsum_kernel(const void* __restrict__ batch, int n) {
    int w = (blockIdx.x * blockDim.x + threadIdx.x) >> 5;
    int lane = threadIdx.x & 31;
    int W = (gridDim.x * blockDim.x) >> 5;
    int L = (n + W - 1) / W;
    int s0 = w * L, e0 = min(s0 + L, n);
    if (s0 >= e0) return;
    const int is64 = g_is64;

    int bcur = (int)load_index(batch, s0, is64);
    float r[8];
    #pragma unroll
    for (int q = 0; q < 8; q++) r[q] = 0.f;
    float dsum = 0.f;

    for (int i = s0; i < e0; i++) {
        int b = (int)load_index(batch, i, is64);
        if (b != bcur) {
            float* pr = &g_pnum[bcur * HID_CH + lane * 8];
            red4(pr, r[0], r[1], r[2], r[3]);
            red4(pr + 4, r[4], r[5], r[6], r[7]);
            if (lane == 0) atomicAdd(&g_denom[bcur], dsum);
            #pragma unroll
            for (int q = 0; q < 8; q++) r[q] = 0.f;
            dsum = 0.f;
            bcur = b;
        }
        float a = expf(g_gate[i] - fdec(g_gmax[b]));
        const float* hr = &g_h2[(size_t)i * HID_CH + lane * 8];
        float4 h0 = *(const float4*)hr;
        float4 h1 = *(const float4*)(hr + 4);
        r[0] += a * h0.x; r[1] += a * h0.y; r[2] += a * h0.z; r[3] += a * h0.w;
        r[4] += a * h1.x; r[5] += a * h1.y; r[6] += a * h1.z; r[7] += a * h1.w;
        dsum += a;
    }
    float* pr = &g_pnum[bcur * HID_CH + lane * 8];
    red4(pr, r[0], r[1], r[2], r[3]);
    red4(pr + 4, r[4], r[5], r[6], r[7]);
    if (lane == 0) atomicAdd(&g_denom[bcur], dsum);
}

// ---------------- pooled = pnum / denom; write to output tail ----------------
__global__ void pool_kernel(float* __restrict__ out, int B) {
    int i = blockIdx.x * blockDim.x + threadIdx.x;
    if (i >= B * HID_CH) return;
    int b = i >> 8;
    float d = g_denom[b];
    float p = (d > 0.f) ? g_pnum[i] / d : 0.f;
    g_pooled[i] = p;
    out[(size_t)B * K_CLS + i] = p;
}

// ---------------- logits = pooled @ Wh + bh  (8 graphs per block, Wh reused 8x) ----------------
__global__ void __launch_bounds__(128) head_kernel(const float* __restrict__ Wh,
                                                   const float* __restrict__ bh,
                                                   float* __restrict__ out, int B) {
    __shared__ float p[8][HID_CH];   // 8 KB
    int kb = blockIdx.x * 128 + threadIdx.x;
    int b0 = blockIdx.y * 8;
    int nb = min(8, B - b0);
    for (int i = threadIdx.x; i < nb * HID_CH; i += 128)
        p[i >> 8][i & 255] = g_pooled[(b0 + (i >> 8)) * HID_CH + (i & 255)];
    __syncthreads();
    if (kb >= K_CLS) return;
    float acc[8];
    #pragma unroll
    for (int j = 0; j < 8; j++) acc[j] = 0.f;
    #pragma unroll 4
    for (int c = 0; c < HID_CH; c++) {
        float wv = Wh[(size_t)c * K_CLS + kb];
        #pragma unroll
        for (int j = 0; j < 8; j++) acc[j] += p[j][c] * wv;
    }
    float bv = bh[kb];
    for (int j = 0; j < nb; j++)
        out[(size_t)(b0 + j) * K_CLS + kb] = acc[j] + bv;
}

// ---------------- launch ----------------
extern "C" void kernel_launch(void* const* d_in, const int* in_sizes, int n_in,
                              void* d_out, int out_size) {
    const float* x     = (const float*)d_in[0];
    const void*  ei    = d_in[1];
    const float* eattr = (const float*)d_in[2];
    const void*  batch = d_in[3];
    const float* We    = (const float*)d_in[4];
    const float* be    = (const float*)d_in[5];
    const float* W1    = (const float*)d_in[6];
    const float* b1    = (const float*)d_in[7];
    const float* W2    = (const float*)d_in[8];
    const float* b2    = (const float*)d_in[9];
    const float* Wg1   = (const float*)d_in[10];
    const float* bg1   = (const float*)d_in[11];
    const float* Wg2   = (const float*)d_in[12];
    const float* bg2   = (const float*)d_in[13];
    const float* Wh    = (const float*)d_in[14];
    const float* bh    = (const float*)d_in[15];
    float* out = (float*)d_out;

    int n = in_sizes[0] / IN_CH;
    int E = in_sizes[2] / ED_CH;
    int B = out_size / (K_CLS + HID_CH);

    prep_kernel<<<dim3(8, 8, 4), dim3(32, 8)>>>(We, W1, W2, Wg1);
    init_kernel<<<2048, 256>>>(x, (const int*)ei, n);

    edge_mma<<<(E + 127) / 128, 256>>>(eattr, ei, x, be, E);

    int mb = (n + 127) / 128;
    gemm_mma<0><<<dim3(2, mb), 256>>>(b1, nullptr, nullptr, nullptr, n);
    gemm_mma<1><<<dim3(2, mb), 256>>>(b2, nullptr, nullptr, nullptr, n);
    gemm_mma<2><<<dim3(1, mb), 256>>>(bg1, Wg2, bg2, batch, n);

    gsum_kernel<<<400, 256>>>(batch, n);
    pool_kernel<<<(B * HID_CH + 255) / 256, 256>>>(out, B);
    head_kernel<<<dim3(8, (B + 7) / 8), 128>>>(Wh, bh, out, B);
}

// round 6
// speedup vs baseline: 3.0669x; 1.1275x over previous
#include <cuda_runtime.h>
#include <cuda_fp16.h>
#include <math.h>

#define IN_CH  128
#define ED_CH  64
#define HID_CH 256
#define K_CLS  1000
#define MAXN   50000
#define MAXB   128

// transposed fp16 weights: [n][k] layouts (offsets in half elements)
#define WE_T_OFF  0          // 128 x 64
#define W1_T_OFF  8192       // 256 x 128
#define W2_T_OFF  40960      // 256 x 256
#define WG1_T_OFF 106496     // 128 x 256

#define STAGE_BYTES 36864    // one (A 18KB + B 18KB) fp16 stage
#define GEMM_DSM    73728    // 2 stages
#define EDGE_DSM    (36864 + 65536)   // 1 stage + 128x128 f32 x-stage

// ---------------- scratch (static device globals; no allocation) ----------------
__device__ float    g_agg[MAXN * IN_CH];     // init = x, edge adds messages -> becomes h
__device__ __half   g_t[MAXN * HID_CH];      // fp16 activations (exactly what gemm<1> would see)
__device__ float    g_h2[MAXN * HID_CH];
__device__ float    g_gate[MAXN];
__device__ unsigned g_gmax[MAXB];
__device__ float    g_denom[MAXB];
__device__ float    g_pnum[MAXB * HID_CH];
__device__ float    g_pooled[MAXB * HID_CH];
__device__ __half   g_wt[139264];
__device__ int      g_is64;

// ---------------- helpers ----------------
__device__ __forceinline__ unsigned fenc(float f) {
    unsigned u = __float_as_uint(f);
    return (u & 0x80000000u) ? ~u : (u | 0x80000000u);
}
__device__ __forceinline__ float fdec(unsigned u) {
    return __uint_as_float((u & 0x80000000u) ? (u ^ 0x80000000u) : ~u);
}
__device__ __forceinline__ void red4(float* p, float a, float b, float c, float d) {
    asm volatile("red.global.add.v4.f32 [%0], {%1,%2,%3,%4};"
                 :: "l"(p), "f"(a), "f"(b), "f"(c), "f"(d) : "memory");
}
__device__ __forceinline__ long long load_index(const void* p, long i, int is64) {
    if (is64) return ((const long long*)p)[i];
    return (long long)((const int*)p)[i];
}
__device__ __forceinline__ unsigned f2h2(float a, float b) {
    __half2 h = __floats2half2_rn(a, b);
    return *(unsigned*)&h;
}
__device__ __forceinline__ void mma16(float* c, const unsigned* a, const unsigned* b) {
    asm volatile("mma.sync.aligned.m16n8k16.row.col.f32.f16.f16.f32 "
                 "{%0,%1,%2,%3}, {%4,%5,%6,%7}, {%8,%9}, {%0,%1,%2,%3};"
                 : "+f"(c[0]), "+f"(c[1]), "+f"(c[2]), "+f"(c[3])
                 : "r"(a[0]), "r"(a[1]), "r"(a[2]), "r"(a[3]), "r"(b[0]), "r"(b[1]));
}
__device__ __forceinline__ void ldsm4(unsigned* r, unsigned addr) {
    asm volatile("ldmatrix.sync.aligned.m8n8.x4.shared.b16 {%0,%1,%2,%3}, [%4];"
                 : "=r"(r[0]), "=r"(r[1]), "=r"(r[2]), "=r"(r[3]) : "r"(addr));
}
__device__ __forceinline__ void cpasync16(unsigned saddr, const void* g) {
    asm volatile("cp.async.cg.shared.global [%0], [%1], 16;" :: "r"(saddr), "l"(g) : "memory");
}
__device__ __forceinline__ void cp_commit() {
    asm volatile("cp.async.commit_group;" ::: "memory");
}
template <int N> __device__ __forceinline__ void cp_wait() {
    asm volatile("cp.async.wait_group %0;" :: "n"(N) : "memory");
}

// fragment smem byte-addresses for ldmatrix (A: [m][k] rows, B: [n][k] rows; stride 72 halves)
__device__ __forceinline__ void frag_addrs(unsigned as_b, unsigned bs_b, int lane,
                                           int wm, int wn, unsigned* aa, unsigned* bb) {
    #pragma unroll
    for (int mi = 0; mi < 2; mi++)
        aa[mi] = as_b + ((wm * 32 + mi * 16 + (lane & 15)) * 72 + (lane >> 4) * 8) * 2;
    #pragma unroll
    for (int nj = 0; nj < 4; nj++)
        bb[nj] = bs_b + ((wn * 64 + nj * 16 + (lane & 7) + ((lane >> 4) & 1) * 8) * 72
                         + ((lane >> 3) & 1) * 8) * 2;
}

// ---------------- weight prep: Wt16[n][k] = half(W[k][n]) ----------------
__global__ void prep_kernel(const float* __restrict__ We, const float* __restrict__ W1,
                            const float* __restrict__ W2, const float* __restrict__ Wg1) {
    __shared__ float t[32][33];
    const float* W; int K, N, off;
    switch (blockIdx.z) {
        case 0: W = We;  K = ED_CH;  N = IN_CH;  off = WE_T_OFF;  break;
        case 1: W = W1;  K = IN_CH;  N = HID_CH; off = W1_T_OFF;  break;
        case 2: W = W2;  K = HID_CH; N = HID_CH; off = W2_T_OFF;  break;
        default:W = Wg1; K = HID_CH; N = 128;    off = WG1_T_OFF; break;
    }
    int n0 = blockIdx.x * 32, k0 = blockIdx.y * 32;
    if (n0 >= N || k0 >= K) return;
    __half* dst = g_wt + off;
    for (int i = threadIdx.y; i < 32; i += 8)
        t[i][threadIdx.x] = W[(size_t)(k0 + i) * N + n0 + threadIdx.x];
    __syncthreads();
    for (int i = threadIdx.y; i < 32; i += 8)
        dst[(size_t)(n0 + i) * K + k0 + threadIdx.x] = __float2half(t[threadIdx.x][i]);
}

// ---------------- init: g_agg = x, zero pool accumulators, sniff index dtype ----------------
__global__ void init_kernel(const float* __restrict__ x, const int* __restrict__ ei, int n) {
    int stride = gridDim.x * blockDim.x;
    int i = blockIdx.x * blockDim.x + threadIdx.x;
    int n4 = n * IN_CH / 4;
    for (int j = i; j < n4; j += stride) ((float4*)g_agg)[j] = ((const float4*)x)[j];
    if (i < MAXB * HID_CH) g_pnum[i] = 0.f;
    if (i < MAXB) { g_denom[i] = 0.f; g_gmax[i] = 0u; }
    if (i == 0) {
        int nz = 0;
        #pragma unroll 8
        for (int k = 0; k < 256; k++) nz += (ei[2 * k + 1] != 0);
        g_is64 = (nz < 16) ? 1 : 0;
    }
}

// ---------------- edge phase: fp16 MMA + cp.async x-prefetch + fused relu/scatter ----------------
__global__ void __launch_bounds__(256) edge_mma(
    const float* __restrict__ eattr, const void* __restrict__ ei,
    const float* __restrict__ x, const float* __restrict__ be, int E)
{
    extern __shared__ char dsm[];
    __half* AsH = (__half*)dsm;                    // [128*72]
    float*  Cs  = (float*)dsm;                     // overlay [64*132]
    float*  Xs  = (float*)(dsm + STAGE_BYTES);     // [128*128]
    __shared__ int s_src[128], s_dst[128];

    const int tid = threadIdx.x;
    const int lane = tid & 31, warp = tid >> 5;
    const int wm = warp & 3, wn = warp >> 2;
    const int r0 = lane >> 2, c0 = lane & 3;
    const int eb = blockIdx.x * 128;
    const int is64 = g_is64;
    const __half* Wt = g_wt + WE_T_OFF;

    unsigned as_b = (unsigned)__cvta_generic_to_shared(dsm);
    unsigned bs_b = as_b + 18432;
    unsigned xs_b = as_b + STAGE_BYTES;
    unsigned aa[2], bb[4];
    frag_addrs(as_b, bs_b, lane, wm, wn, aa, bb);

    // indices
    if (tid < 128) {
        int eg = eb + tid;
        if (eg < E) {
            s_src[tid] = (int)load_index(ei, eg, is64);
            s_dst[tid] = (int)load_index(ei, (long)E + eg, is64);
        } else { s_src[tid] = 0; s_dst[tid] = 0; }
    }

    // B: We_t (128n x 64k halves), group 0
    #pragma unroll
    for (int i = 0; i < 4; i++) {
        int f = tid + i * 256;
        int n = f >> 3, kk = (f & 7) * 8;
        cpasync16(bs_b + (n * 72 + kk) * 2, &Wt[(size_t)n * ED_CH + kk]);
    }
    cp_commit();

    // A: edge_attr (128 x 64), f32 -> half2 into smem
    #pragma unroll
    for (int i = 0; i < 4; i++) {
        int f = tid + i * 256;
        int row = f >> 3, kk = (f & 7) * 8;
        int eg = eb + row;
        float4 v0 = make_float4(0.f, 0.f, 0.f, 0.f), v1 = v0;
        if (eg < E) {
            v0 = *(const float4*)&eattr[(size_t)eg * ED_CH + kk];
            v1 = *(const float4*)&eattr[(size_t)eg * ED_CH + kk + 4];
        }
        uint4 h;
        h.x = f2h2(v0.x, v0.y); h.y = f2h2(v0.z, v0.w);
        h.z = f2h2(v1.x, v1.y); h.w = f2h2(v1.z, v1.w);
        *(uint4*)&AsH[row * 72 + kk] = h;
    }
    __syncthreads();   // s_src visible to all

    // x[src] prefetch: 128 rows x 512B via cp.async, group 1 (hidden under MMA)
    #pragma unroll
    for (int i = 0; i < 16; i++) {
        int f = tid + i * 256;
        int row = f >> 5, seg = f & 31;
        cpasync16(xs_b + (row * 128 + seg * 4) * 4, &x[(size_t)s_src[row] * IN_CH + seg * 4]);
    }
    cp_commit();

    cp_wait<1>();      // B arrived (x may still be in flight)
    __syncthreads();

    float acc[2][8][4];
    #pragma unroll
    for (int mi = 0; mi < 2; mi++)
        #pragma unroll
        for (int ni = 0; ni < 8; ni++)
            #pragma unroll
            for (int q = 0; q < 4; q++) acc[mi][ni][q] = 0.f;

    #pragma unroll
    for (int ks = 0; ks < 4; ks++) {
        unsigned a[2][4], b[4][4];
        ldsm4(a[0], aa[0] + ks * 32);
        ldsm4(a[1], aa[1] + ks * 32);
        #pragma unroll
        for (int j = 0; j < 4; j++) ldsm4(b[j], bb[j] + ks * 32);
        #pragma unroll
        for (int mi = 0; mi < 2; mi++)
            #pragma unroll
            for (int ni = 0; ni < 8; ni++)
                mma16(acc[mi][ni], a[mi], &b[ni >> 1][(ni & 1) * 2]);
    }
    cp_wait<0>();      // x arrived
    __syncthreads();   // MMA smem reads done -> Cs overlay safe

    const float4 bev = *(const float4*)&be[lane * 4];

    // epilogue in 2 phases of 64 edge-rows (Cs overlays A/B stage; Xs separate)
    #pragma unroll
    for (int p = 0; p < 2; p++) {
        if ((wm >> 1) == p) {
            #pragma unroll
            for (int mi = 0; mi < 2; mi++)
                #pragma unroll
                for (int ni = 0; ni < 8; ni++) {
                    int r = (wm & 1) * 32 + mi * 16 + r0;
                    int col = wn * 64 + ni * 8 + 2 * c0;
                    Cs[r * 132 + col]           = acc[mi][ni][0];
                    Cs[r * 132 + col + 1]       = acc[mi][ni][1];
                    Cs[(r + 8) * 132 + col]     = acc[mi][ni][2];
                    Cs[(r + 8) * 132 + col + 1] = acc[mi][ni][3];
                }
        }
        __syncthreads();
        #pragma unroll
        for (int half = 0; half < 2; half++) {
            #pragma unroll
            for (int j = 0; j < 4; j++) {
                int el = warp * 8 + half * 4 + j;
                int eg = eb + p * 64 + el;
                if (eg < E) {
                    int d = s_dst[p * 64 + el];
                    float4 cv = *(const float4*)&Cs[el * 132 + lane * 4];
                    float4 xv = *(const float4*)&Xs[(p * 64 + el) * 128 + lane * 4];
                    red4(&g_agg[(size_t)d * IN_CH + lane * 4],
                         fmaxf(cv.x + bev.x + xv.x, 0.f),
                         fmaxf(cv.y + bev.y + xv.y, 0.f),
                         fmaxf(cv.z + bev.z + xv.z, 0.f),
                         fmaxf(cv.w + bev.w + xv.w, 0.f));
                }
            }
        }
        __syncthreads();
    }
}

// ---------------- fp16 tensor-core GEMM for node MLPs (2-stage pipelined) ----------------
// MODE 0: t16 = relu(h  @ W1 + b1)   K=128 N=256  (h == g_agg f32; t stored fp16)
// MODE 1: h2  =       t @ W2 + b2    K=256 N=256  (A = g_t fp16 via cp.async)
// MODE 2: gate = relu(h2 @ Wg1 + bg1) @ Wg2 + bg2  K=256 N=128 (fused; gate + gmax)
template <int MODE>
__global__ void __launch_bounds__(256) gemm_mma(const float* __restrict__ bias,
                                                const float* __restrict__ Wg2,
                                                const float* __restrict__ bg2,
                                                const void* __restrict__ batch, int M)
{
    constexpr int K = (MODE == 0) ? 128 : 256;
    constexpr int N = (MODE == 2) ? 128 : 256;
    constexpr int NK = K / 64;
    const float* __restrict__ A = (MODE == 0) ? g_agg : g_h2;   // f32 A (MODE 0/2)
    const __half* Wt = g_wt + ((MODE == 0) ? W1_T_OFF : (MODE == 1) ? W2_T_OFF : WG1_T_OFF);

    extern __shared__ char dsm[];
    float* Cs = (float*)dsm;

    const int tid = threadIdx.x;
    const int lane = tid & 31, warp = tid >> 5;
    const int wm = warp & 3, wn = warp >> 2;
    const int r0 = lane >> 2, c0 = lane & 3;
    const int bm = blockIdx.y * 128, bn = blockIdx.x * 128;

    unsigned as_b = (unsigned)__cvta_generic_to_shared(dsm);
    unsigned bs_b = as_b + 18432;
    unsigned aa[2], bb[4];
    frag_addrs(as_b, bs_b, lane, wm, wn, aa, bb);

    float acc[2][8][4];
    #pragma unroll
    for (int mi = 0; mi < 2; mi++)
        #pragma unroll
        for (int ni = 0; ni < 8; ni++)
            #pragma unroll
            for (int q = 0; q < 4; q++) acc[mi][ni][q] = 0.f;

    // ---- chunk issue (B always cp.async; A cp.async for MODE 1, LDG+cvt otherwise) ----
    auto issue_chunk = [&](int c, int s) {
        unsigned sb = (unsigned)(s * STAGE_BYTES);
        #pragma unroll
        for (int i = 0; i < 4; i++) {
            int f = tid + i * 256;
            int n = f >> 3, kk = (f & 7) * 8;
            cpasync16(bs_b + sb + (n * 72 + kk) * 2, &Wt[(size_t)(bn + n) * K + c * 64 + kk]);
        }
        if constexpr (MODE == 1) {
            #pragma unroll
            for (int i = 0; i < 4; i++) {
                int f = tid + i * 256;
                int row = f >> 3, kk = (f & 7) * 8;
                cpasync16(as_b + sb + (row * 72 + kk) * 2,
                          &g_t[(size_t)(bm + row) * K + c * 64 + kk]);
            }
        } else {
            #pragma unroll
            for (int i = 0; i < 4; i++) {
                int f = tid + i * 256;
                int row = f >> 3, kk = (f & 7) * 8;
                int gm = bm + row;
                float4 v0 = make_float4(0.f, 0.f, 0.f, 0.f), v1 = v0;
                if (gm < M) {
                    v0 = *(const float4*)&A[(size_t)gm * K + c * 64 + kk];
                    v1 = *(const float4*)&A[(size_t)gm * K + c * 64 + kk + 4];
                }
                uint4 h;
                h.x = f2h2(v0.x, v0.y); h.y = f2h2(v0.z, v0.w);
                h.z = f2h2(v1.x, v1.y); h.w = f2h2(v1.z, v1.w);
                *(uint4*)(dsm + sb + (row * 72 + kk) * 2) = h;
            }
        }
        cp_commit();
    };

    issue_chunk(0, 0);
    #pragma unroll
    for (int c = 0; c < NK; c++) {
        int cur = c & 1;
        if (c + 1 < NK) { issue_chunk(c + 1, cur ^ 1); cp_wait<1>(); }
        else            { cp_wait<0>(); }
        __syncthreads();
        unsigned sb = (unsigned)(cur * STAGE_BYTES);
        #pragma unroll
        for (int ks = 0; ks < 4; ks++) {
            unsigned a[2][4], b[4][4];
            ldsm4(a[0], aa[0] + sb + ks * 32);
            ldsm4(a[1], aa[1] + sb + ks * 32);
            #pragma unroll
            for (int j = 0; j < 4; j++) ldsm4(b[j], bb[j] + sb + ks * 32);
            #pragma unroll
            for (int mi = 0; mi < 2; mi++)
                #pragma unroll
                for (int ni = 0; ni < 8; ni++)
                    mma16(acc[mi][ni], a[mi], &b[ni >> 1][(ni & 1) * 2]);
        }
        __syncthreads();
    }

    if constexpr (MODE == 0) {
        // relu + bias, store fp16 to g_t
        #pragma unroll
        for (int mi = 0; mi < 2; mi++) {
            #pragma unroll
            for (int ni = 0; ni < 8; ni++) {
                int row = bm + wm * 32 + mi * 16 + r0;
                int col = bn + wn * 64 + ni * 8 + 2 * c0;
                float bx = bias[col], by = bias[col + 1];
                float v0 = fmaxf(acc[mi][ni][0] + bx, 0.f);
                float v1 = fmaxf(acc[mi][ni][1] + by, 0.f);
                float v2 = fmaxf(acc[mi][ni][2] + bx, 0.f);
                float v3 = fmaxf(acc[mi][ni][3] + by, 0.f);
                if (row < M)     *(__half2*)&g_t[(size_t)row * N + col]       = __floats2half2_rn(v0, v1);
                if (row + 8 < M) *(__half2*)&g_t[(size_t)(row + 8) * N + col] = __floats2half2_rn(v2, v3);
            }
        }
    } else if constexpr (MODE == 1) {
        #pragma unroll
        for (int mi = 0; mi < 2; mi++) {
            #pragma unroll
            for (int ni = 0; ni < 8; ni++) {
                int row = bm + wm * 32 + mi * 16 + r0;
                int col = bn + wn * 64 + ni * 8 + 2 * c0;
                float bx = bias[col], by = bias[col + 1];
                float v0 = acc[mi][ni][0] + bx, v1 = acc[mi][ni][1] + by;
                float v2 = acc[mi][ni][2] + bx, v3 = acc[mi][ni][3] + by;
                if (row < M)     *(float2*)&g_h2[(size_t)row * N + col]       = make_float2(v0, v1);
                if (row + 8 < M) *(float2*)&g_h2[(size_t)(row + 8) * N + col] = make_float2(v2, v3);
            }
        }
    } else {
        // fused gate: g1 tile (128 x 128) -> smem in 2 phases, warp-per-row dot with Wg2
        const float4 wgv = *(const float4*)&Wg2[lane * 4];
        const float bg2v = bg2[0];
        const int is64 = g_is64;
        #pragma unroll
        for (int p = 0; p < 2; p++) {
            if ((wm >> 1) == p) {
                #pragma unroll
                for (int mi = 0; mi < 2; mi++)
                    #pragma unroll
                    for (int ni = 0; ni < 8; ni++) {
                        int r = (wm & 1) * 32 + mi * 16 + r0;
                        int col = wn * 64 + ni * 8 + 2 * c0;
                        float bx = bias[col], by = bias[col + 1];
                        Cs[r * 132 + col]           = fmaxf(acc[mi][ni][0] + bx, 0.f);
                        Cs[r * 132 + col + 1]       = fmaxf(acc[mi][ni][1] + by, 0.f);
                        Cs[(r + 8) * 132 + col]     = fmaxf(acc[mi][ni][2] + bx, 0.f);
                        Cs[(r + 8) * 132 + col + 1] = fmaxf(acc[mi][ni][3] + by, 0.f);
                    }
            }
            __syncthreads();
            #pragma unroll 2
            for (int j = 0; j < 8; j++) {
                int el = warp * 8 + j;
                int row = bm + p * 64 + el;
                if (row < M) {
                    float4 cvv = *(const float4*)&Cs[el * 132 + lane * 4];
                    float s = cvv.x * wgv.x + cvv.y * wgv.y + cvv.z * wgv.z + cvv.w * wgv.w;
                    #pragma unroll
                    for (int o = 16; o; o >>= 1) s += __shfl_xor_sync(0xffffffffu, s, o);
                    if (lane == 0) {
                        float g = s + bg2v;
                        g_gate[row] = g;
                        int b = (int)load_index(batch, row, is64);
                        atomicMax(&g_gmax[b], fenc(g));
                    }
                }
            }
            __syncthreads();
        }
    }
}

// ---------------- softmax numerator + weighted sum: warp strips with run-length flush ----------------
__global__ void gsum_kernel(const void* __restrict__ batch, int n) {
    int w = (blockIdx.x * blockDim.x + threadIdx.x) >> 5;
    int lane = threadIdx.x & 31;
    int W = (gridDim.x * blockDim.x) >> 5;
    int L = (n + W - 1) / W;
    int s0 = w * L, e0 = min(s0 + L, n);
    if (s0 >= e0) return;
    const int is64 = g_is64;

    int bcur = (int)load_index(batch, s0, is64);
    float r[8];
    #pragma unroll
    for (int q = 0; q < 8; q++) r[q] = 0.f;
    float dsum = 0.f;

    for (int i = s0; i < e0; i++) {
        int b = (int)load_index(batch, i, is64);
        if (b != bcur) {
            float* pr = &g_pnum[bcur * HID_CH + lane * 8];
            red4(pr, r[0], r[1], r[2], r[3]);
            red4(pr + 4, r[4], r[5], r[6], r[7]);
            if (lane == 0) atomicAdd(&g_denom[bcur], dsum);
            #pragma unroll
            for (int q = 0; q < 8; q++) r[q] = 0.f;
            dsum = 0.f;
            bcur = b;
        }
        float a = expf(g_gate[i] - fdec(g_gmax[b]));
        const float* hr = &g_h2[(size_t)i * HID_CH + lane * 8];
        float4 h0 = *(const float4*)hr;
        float4 h1 = *(const float4*)(hr + 4);
        r[0] += a * h0.x; r[1] += a * h0.y; r[2] += a * h0.z; r[3] += a * h0.w;
        r[4] += a * h1.x; r[5] += a * h1.y; r[6] += a * h1.z; r[7] += a * h1.w;
        dsum += a;
    }
    float* pr = &g_pnum[bcur * HID_CH + lane * 8];
    red4(pr, r[0], r[1], r[2], r[3]);
    red4(pr + 4, r[4], r[5], r[6], r[7]);
    if (lane == 0) atomicAdd(&g_denom[bcur], dsum);
}

// ---------------- pooled = pnum / denom; write to output tail ----------------
__global__ void pool_kernel(float* __restrict__ out, int B) {
    int i = blockIdx.x * blockDim.x + threadIdx.x;
    if (i >= B * HID_CH) return;
    int b = i >> 8;
    float d = g_denom[b];
    float p = (d > 0.f) ? g_pnum[i] / d : 0.f;
    g_pooled[i] = p;
    out[(size_t)B * K_CLS + i] = p;
}

// ---------------- logits = pooled @ Wh + bh  (8 graphs per block, Wh reused 8x) ----------------
__global__ void __launch_bounds__(128) head_kernel(const float* __restrict__ Wh,
                                                   const float* __restrict__ bh,
                                                   float* __restrict__ out, int B) {
    __shared__ float p[8][HID_CH];   // 8 KB
    int kb = blockIdx.x * 128 + threadIdx.x;
    int b0 = blockIdx.y * 8;
    int nb = min(8, B - b0);
    for (int i = threadIdx.x; i < nb * HID_CH; i += 128)
        p[i >> 8][i & 255] = g_pooled[(b0 + (i >> 8)) * HID_CH + (i & 255)];
    __syncthreads();
    if (kb >= K_CLS) return;
    float acc[8];
    #pragma unroll
    for (int j = 0; j < 8; j++) acc[j] = 0.f;
    #pragma unroll 4
    for (int c = 0; c < HID_CH; c++) {
        float wv = Wh[(size_t)c * K_CLS + kb];
        #pragma unroll
        for (int j = 0; j < 8; j++) acc[j] += p[j][c] * wv;
    }
    float bv = bh[kb];
    for (int j = 0; j < nb; j++)
        out[(size_t)(b0 + j) * K_CLS + kb] = acc[j] + bv;
}

// ---------------- launch ----------------
extern "C" void kernel_launch(void* const* d_in, const int* in_sizes, int n_in,
                              void* d_out, int out_size) {
    const float* x     = (const float*)d_in[0];
    const void*  ei    = d_in[1];
    const float* eattr = (const float*)d_in[2];
    const void*  batch = d_in[3];
    const float* We    = (const float*)d_in[4];
    const float* be    = (const float*)d_in[5];
    const float* W1    = (const float*)d_in[6];
    const float* b1    = (const float*)d_in[7];
    const float* W2    = (const float*)d_in[8];
    const float* b2    = (const float*)d_in[9];
    const float* Wg1   = (const float*)d_in[10];
    const float* bg1   = (const float*)d_in[11];
    const float* Wg2   = (const float*)d_in[12];
    const float* bg2   = (const float*)d_in[13];
    const float* Wh    = (const float*)d_in[14];
    const float* bh    = (const float*)d_in[15];
    float* out = (float*)d_out;

    int n = in_sizes[0] / IN_CH;
    int E = in_sizes[2] / ED_CH;
    int B = out_size / (K_CLS + HID_CH);

    cudaFuncSetAttribute(edge_mma, cudaFuncAttributeMaxDynamicSharedMemorySize, EDGE_DSM);
    cudaFuncSetAttribute(gemm_mma<0>, cudaFuncAttributeMaxDynamicSharedMemorySize, GEMM_DSM);
    cudaFuncSetAttribute(gemm_mma<1>, cudaFuncAttributeMaxDynamicSharedMemorySize, GEMM_DSM);
    cudaFuncSetAttribute(gemm_mma<2>, cudaFuncAttributeMaxDynamicSharedMemorySize, GEMM_DSM);

    prep_kernel<<<dim3(8, 8, 4), dim3(32, 8)>>>(We, W1, W2, Wg1);
    init_kernel<<<2048, 256>>>(x, (const int*)ei, n);

    edge_mma<<<(E + 127) / 128, 256, EDGE_DSM>>>(eattr, ei, x, be, E);

    int mb = (n + 127) / 128;
    gemm_mma<0><<<dim3(2, mb), 256, GEMM_DSM>>>(b1, nullptr, nullptr, nullptr, n);
    gemm_mma<1><<<dim3(2, mb), 256, GEMM_DSM>>>(b2, nullptr, nullptr, nullptr, n);
    gemm_mma<2><<<dim3(1, mb), 256, GEMM_DSM>>>(bg1, Wg2, bg2, batch, n);

    gsum_kernel<<<400, 256>>>(batch, n);
    pool_kernel<<<(B * HID_CH + 255) / 256, 256>>>(out, B);
    head_kernel<<<dim3(8, (B + 7) / 8), 128>>>(Wh, bh, out, B);
}